// round 1
// baseline (speedup 1.0000x reference)
#include <cuda_runtime.h>

// Model_53283364274775: per-relation AO MLPs + shared UI MLP + dot head.
// B=8192 pairs, N=32 AO triples each, D=64, H=128, O=64, R=3.
//
// Strategy (round 1 baseline): compute ONLY the selected relation per (b,n)
// element (1/3 of the reference's dense work). Each CTA owns 128 rows
// (= 4 consecutive b's, all their n), counting-sorts them by relation into
// padded slot ranges, and runs per-relation sub-GEMMs against smem-resident
// weights with 4x4 register blocking (float4 LDS on both operands).

#define B_   8192
#define N_   32
#define TOT  (B_ * N_)
#define SLOPE 0.01f

#define UI_SP 68    // padded slot stride for ui kernel (64 rows)
#define AO_SP 140   // padded slot stride for ao kernel (128 rows + 4-align pad per relation)

__device__ int   g_s32[TOT];
__device__ float g_ui[B_ * 64];

__device__ __forceinline__ float lrelu(float x) { return x >= 0.f ? x : SLOPE * x; }

// ---------------------------------------------------------------------------
// s dtype normalization: reference declares int64 but JAX without x64 yields
// int32. Detect layout by scanning odd 32-bit words of the first 128 values:
// int64 little-endian => all high words are 0 (values are 0..2); int32 =>
// odd positions are independent random values in 0..2 (P(all zero) ~ 3^-128).
// ---------------------------------------------------------------------------
__global__ void prep_s_kernel(const int* __restrict__ s_raw) {
    __shared__ int sIs64;
    if (threadIdx.x == 0) {
        int nz = 0;
        #pragma unroll
        for (int i = 1; i < 256; i += 2) nz |= s_raw[i];
        sIs64 = (nz == 0) ? 1 : 0;
    }
    __syncthreads();
    int idx = blockIdx.x * blockDim.x + threadIdx.x;
    if (idx < TOT)
        g_s32[idx] = sIs64 ? s_raw[2 * idx] : s_raw[idx];
}

// ---------------------------------------------------------------------------
// UI branch: ui = lrelu(lrelu([u,i] @ W0 + b0) @ W1 + b1), shared weights.
// CTA = 256 threads, 64 rows. Transposed x in smem for float4 row-group loads.
// ---------------------------------------------------------------------------
__global__ void __launch_bounds__(256) ui_kernel(
    const float* __restrict__ u, const float* __restrict__ iv,
    const float* __restrict__ W0, const float* __restrict__ b0,
    const float* __restrict__ W1, const float* __restrict__ b1)
{
    extern __shared__ float sm[];
    float* sxT = sm;                    // [128][UI_SP]
    float* shT = sm + 128 * UI_SP;      // [128][UI_SP]
    float* sw  = sm + 2 * 128 * UI_SP;  // 16384 floats (reused: W0 then W1)
    float* sb  = sw + 16384;            // 128

    const int tid = threadIdx.x;
    const int rowbase = blockIdx.x * 64;

    // load x transposed: sxT[d][m] = concat(u,i)[row m][d]
    for (int idx = tid; idx < 64 * 64; idx += 256) {
        int m = idx >> 6, d = idx & 63;
        int g = (rowbase + m) * 64 + d;
        sxT[d * UI_SP + m]        = u[g];
        sxT[(64 + d) * UI_SP + m] = iv[g];
    }
    for (int idx = tid; idx < 4096; idx += 256)
        ((float4*)sw)[idx] = ((const float4*)W0)[idx];
    if (tid < 128) sb[tid] = b0[tid];
    __syncthreads();

    // layer 1: h[m][c] ; tiles of 4 rows x 4 cols; 16 m-groups x 32 c-groups
    for (int t = tid; t < 512; t += 256) {
        int m4 = (t >> 5) << 2, c4 = (t & 31) << 2;
        float acc[4][4] = {};
        #pragma unroll 8
        for (int k = 0; k < 128; k++) {
            float4 x4 = *(const float4*)(sxT + k * UI_SP + m4);
            float4 w4 = *(const float4*)(sw + k * 128 + c4);
            float xr[4] = {x4.x, x4.y, x4.z, x4.w};
            float wr[4] = {w4.x, w4.y, w4.z, w4.w};
            #pragma unroll
            for (int si = 0; si < 4; si++)
                #pragma unroll
                for (int ci = 0; ci < 4; ci++)
                    acc[si][ci] = fmaf(xr[si], wr[ci], acc[si][ci]);
        }
        #pragma unroll
        for (int ci = 0; ci < 4; ci++) {
            float bv = sb[c4 + ci];
            #pragma unroll
            for (int si = 0; si < 4; si++)
                shT[(c4 + ci) * UI_SP + m4 + si] = lrelu(acc[si][ci] + bv);
        }
    }
    __syncthreads();

    for (int idx = tid; idx < 2048; idx += 256)
        ((float4*)sw)[idx] = ((const float4*)W1)[idx];
    if (tid < 64) sb[tid] = b1[tid];
    __syncthreads();

    // layer 2: 16 m-groups x 16 o-groups = 256 tiles
    for (int t = tid; t < 256; t += 256) {
        int m4 = (t >> 4) << 2, o4 = (t & 15) << 2;
        float acc[4][4] = {};
        #pragma unroll 8
        for (int k = 0; k < 128; k++) {
            float4 x4 = *(const float4*)(shT + k * UI_SP + m4);
            float4 w4 = *(const float4*)(sw + k * 64 + o4);
            float xr[4] = {x4.x, x4.y, x4.z, x4.w};
            float wr[4] = {w4.x, w4.y, w4.z, w4.w};
            #pragma unroll
            for (int si = 0; si < 4; si++)
                #pragma unroll
                for (int ci = 0; ci < 4; ci++)
                    acc[si][ci] = fmaf(xr[si], wr[ci], acc[si][ci]);
        }
        #pragma unroll
        for (int si = 0; si < 4; si++)
            #pragma unroll
            for (int ci = 0; ci < 4; ci++)
                g_ui[(rowbase + m4 + si) * 64 + o4 + ci] =
                    lrelu(acc[si][ci] + sb[o4 + ci]);
    }
}

// ---------------------------------------------------------------------------
// AO branch + dot head. CTA = 512 threads, 128 rows (4 consecutive b).
// Rows counting-sorted by relation into 4-aligned slot ranges; per-relation
// sub-GEMMs against smem weights; deterministic per-colgroup partial sums.
// ---------------------------------------------------------------------------
__global__ void __launch_bounds__(512) ao_kernel(
    const float* __restrict__ a, const float* __restrict__ o,
    const float* __restrict__ W0, const float* __restrict__ b0,
    const float* __restrict__ W1, const float* __restrict__ b1,
    float* __restrict__ out)
{
    extern __shared__ float sm[];
    float* sxT   = sm;                       // [128][AO_SP] = 17920
    float* shT   = sm + 128 * AO_SP;         // [128][AO_SP] = 17920
    float* sw    = sm + 2 * 128 * AO_SP;     // 16384 (W0[r] / W1[r])
    float* sb    = sw + 16384;               // 128
    float* sui   = sb + 128;                 // 256 = 4 b's x 64
    float* spart = sui + 256;                // [AO_SP][16] partial dots

    __shared__ int srel[128];
    __shared__ int slot2row[AO_SP];
    __shared__ int row2slot[128];
    __shared__ int soff[3], sg4[3];

    const int tid = threadIdx.x;
    const int rowbase = blockIdx.x * 128;
    const int bbase = rowbase >> 5;   // first b of this CTA

    if (tid < 128) srel[tid] = g_s32[rowbase + tid];
    __syncthreads();

    if (tid == 0) {
        int c[3] = {0, 0, 0};
        for (int m = 0; m < 128; m++) c[srel[m]]++;
        int l0 = (c[0] + 3) & ~3, l1 = (c[1] + 3) & ~3, l2 = (c[2] + 3) & ~3;
        soff[0] = 0; soff[1] = l0; soff[2] = l0 + l1;
        sg4[0] = l0 >> 2; sg4[1] = l1 >> 2; sg4[2] = l2 >> 2;
        int pos[3] = {soff[0], soff[1], soff[2]};
        for (int s = 0; s < AO_SP; s++) slot2row[s] = -1;
        for (int m = 0; m < 128; m++) {
            int r = srel[m];
            slot2row[pos[r]] = m;
            row2slot[m] = pos[r];
            pos[r]++;
        }
    }
    // zero sxT so padded dummy slots contribute 0 (concurrent with sort)
    for (int idx = tid; idx < 128 * AO_SP / 4; idx += 512)
        ((float4*)sxT)[idx] = make_float4(0.f, 0.f, 0.f, 0.f);
    __syncthreads();

    // load a/o rows transposed into sorted slots
    for (int idx = tid; idx < 128 * 64; idx += 512) {
        int m = idx >> 6, d = idx & 63;
        int slot = row2slot[m];
        int g = (rowbase + m) * 64 + d;
        sxT[d * AO_SP + slot]        = a[g];
        sxT[(64 + d) * AO_SP + slot] = o[g];
    }
    if (tid < 256) sui[tid] = g_ui[bbase * 64 + tid];
    __syncthreads();

    // layer 1: per relation, W0[r] in smem, compute h for that relation's slots
    for (int r = 0; r < 3; r++) {
        for (int idx = tid; idx < 4096; idx += 512)
            ((float4*)sw)[idx] = ((const float4*)(W0 + r * 16384))[idx];
        if (tid < 128) sb[tid] = b0[r * 128 + tid];
        __syncthreads();

        int ng = sg4[r], base = soff[r];
        int tiles = ng * 32;  // slot-groups x 32 col-groups
        for (int t = tid; t < tiles; t += 512) {
            int s4 = base + ((t >> 5) << 2), c4 = (t & 31) << 2;
            float acc[4][4] = {};
            #pragma unroll 8
            for (int k = 0; k < 128; k++) {
                float4 x4 = *(const float4*)(sxT + k * AO_SP + s4);
                float4 w4 = *(const float4*)(sw + k * 128 + c4);
                float xr[4] = {x4.x, x4.y, x4.z, x4.w};
                float wr[4] = {w4.x, w4.y, w4.z, w4.w};
                #pragma unroll
                for (int si = 0; si < 4; si++)
                    #pragma unroll
                    for (int ci = 0; ci < 4; ci++)
                        acc[si][ci] = fmaf(xr[si], wr[ci], acc[si][ci]);
            }
            #pragma unroll
            for (int ci = 0; ci < 4; ci++) {
                float bv = sb[c4 + ci];
                #pragma unroll
                for (int si = 0; si < 4; si++)
                    shT[(c4 + ci) * AO_SP + s4 + si] = lrelu(acc[si][ci] + bv);
            }
        }
        __syncthreads();
    }

    // layer 2 fused with dot(ui): per relation, W1[r] in smem.
    // Each tile produces a partial dot per slot into spart[slot][colgroup]
    // (unique writer per cell -> deterministic).
    for (int r = 0; r < 3; r++) {
        for (int idx = tid; idx < 2048; idx += 512)
            ((float4*)sw)[idx] = ((const float4*)(W1 + r * 8192))[idx];
        if (tid < 64) sb[tid] = b1[r * 64 + tid];
        __syncthreads();

        int ng = sg4[r], base = soff[r];
        int tiles = ng * 16;  // slot-groups x 16 col-groups (64 cols)
        for (int t = tid; t < tiles; t += 512) {
            int s4 = base + ((t >> 4) << 2), c4 = (t & 15) << 2;
            float acc[4][4] = {};
            #pragma unroll 8
            for (int k = 0; k < 128; k++) {
                float4 x4 = *(const float4*)(shT + k * AO_SP + s4);
                float4 w4 = *(const float4*)(sw + k * 64 + c4);
                float xr[4] = {x4.x, x4.y, x4.z, x4.w};
                float wr[4] = {w4.x, w4.y, w4.z, w4.w};
                #pragma unroll
                for (int si = 0; si < 4; si++)
                    #pragma unroll
                    for (int ci = 0; ci < 4; ci++)
                        acc[si][ci] = fmaf(xr[si], wr[ci], acc[si][ci]);
            }
            #pragma unroll
            for (int si = 0; si < 4; si++) {
                int m = slot2row[s4 + si];
                float p = 0.f;
                if (m >= 0) {
                    int bb = m >> 5;
                    #pragma unroll
                    for (int ci = 0; ci < 4; ci++) {
                        float v = lrelu(acc[si][ci] + sb[c4 + ci]);
                        p = fmaf(v, sui[bb * 64 + c4 + ci], p);
                    }
                }
                spart[(s4 + si) * 16 + (c4 >> 2)] = p;
            }
        }
        __syncthreads();
    }

    // final: fixed-order reduction of 16 partials per row
    if (tid < 128) {
        int slot = row2slot[tid];
        float p = 0.f;
        #pragma unroll
        for (int g = 0; g < 16; g++) p += spart[slot * 16 + g];
        out[rowbase + tid] = p;
    }
}

// ---------------------------------------------------------------------------
extern "C" void kernel_launch(void* const* d_in, const int* in_sizes, int n_in,
                              void* d_out, int out_size) {
    const float* u    = (const float*)d_in[0];
    const float* iv   = (const float*)d_in[1];
    const float* a    = (const float*)d_in[2];
    const float* o    = (const float*)d_in[3];
    const int*   s    = (const int*)  d_in[4];   // int32 or int64 view; normalized by prep
    const float* aoW0 = (const float*)d_in[5];
    const float* aob0 = (const float*)d_in[6];
    const float* aoW1 = (const float*)d_in[7];
    const float* aob1 = (const float*)d_in[8];
    const float* uiW0 = (const float*)d_in[9];
    const float* uib0 = (const float*)d_in[10];
    const float* uiW1 = (const float*)d_in[11];
    const float* uib1 = (const float*)d_in[12];
    float* out = (float*)d_out;

    const size_t ui_smem = (size_t)(128 * UI_SP * 2 + 16384 + 128) * sizeof(float);
    const size_t ao_smem = (size_t)(128 * AO_SP * 2 + 16384 + 128 + 256 + AO_SP * 16) * sizeof(float);

    cudaFuncSetAttribute((const void*)ui_kernel,
                         cudaFuncAttributeMaxDynamicSharedMemorySize, (int)ui_smem);
    cudaFuncSetAttribute((const void*)ao_kernel,
                         cudaFuncAttributeMaxDynamicSharedMemorySize, (int)ao_smem);

    prep_s_kernel<<<TOT / 256, 256>>>(s);
    ui_kernel<<<B_ / 64, 256, ui_smem>>>(u, iv, uiW0, uib0, uiW1, uib1);
    ao_kernel<<<TOT / 128, 512, ao_smem>>>(a, o, aoW0, aob0, aoW1, aob1, out);
}

// round 4
// speedup vs baseline: 1.8215x; 1.8215x over previous
#include <cuda_runtime.h>
#include <cuda_bf16.h>
#include <cstdint>

// Model_53283364274775 on GB300 (compiled at plain sm_103 PTX target, so no
// tcgen05): AO branch via warp-level mma.sync bf16 HMMA, 3-term hi/lo split,
// fp32 accumulate. Global relation counting-sort -> relation-uniform CTAs.

#define B_   8192
#define N_   32
#define TOT  (B_ * N_)
#define SLOPE 0.01f
#define UI_SP 68
#define NCTA_AO 2051

__device__ int   g_s32[TOT];
__device__ int   g_cnt[3];
__device__ int   g_pos[3];
__device__ int   g_off[4];
__device__ int   g_perm[TOT + 512];
__device__ float g_ui[B_ * 64];
// Per-relation prebuilt smem weight image (pre-swizzled bf16 hi/lo):
// [0,32K) W0hi  [32K,64K) W0lo  [64K,80K) W1hi  [80K,96K) W1lo ; 96KB each
__device__ float4 g_wimg[3 * 6144];

__device__ __forceinline__ float lrelu(float x) { return x >= 0.f ? x : SLOPE * x; }

__device__ __forceinline__ uint32_t smem_to_u32(const void* p) {
    uint32_t a;
    asm("{ .reg .u64 t; cvta.to.shared.u64 t, %1; cvt.u32.u64 %0, t; }"
        : "=r"(a) : "l"(p));
    return a;
}
__device__ __forceinline__ void ldsm_x4(uint32_t& r0, uint32_t& r1,
                                        uint32_t& r2, uint32_t& r3, uint32_t addr) {
    asm volatile("ldmatrix.sync.aligned.m8n8.x4.shared.b16 {%0,%1,%2,%3}, [%4];"
        : "=r"(r0), "=r"(r1), "=r"(r2), "=r"(r3) : "r"(addr));
}
__device__ __forceinline__ void mma_bf16(float* d, const uint32_t* a4,
                                         uint32_t b0, uint32_t b1) {
    asm volatile("mma.sync.aligned.m16n8k16.row.col.f32.bf16.bf16.f32 "
        "{%0,%1,%2,%3}, {%4,%5,%6,%7}, {%8,%9}, {%0,%1,%2,%3};"
        : "+f"(d[0]), "+f"(d[1]), "+f"(d[2]), "+f"(d[3])
        : "r"(a4[0]), "r"(a4[1]), "r"(a4[2]), "r"(a4[3]), "r"(b0), "r"(b1));
}
// 256B rows of bf16, XOR swizzle on 16B chunks: conflict-free ldmatrix
__device__ __forceinline__ uint32_t sw_off(int row, int chunk16) {
    return (uint32_t)(row * 256 + ((chunk16 ^ (row & 7)) << 4));
}
// pack (f0,f1) -> bf16 hi pair, residual lo pair (little-endian: f0 low half)
__device__ __forceinline__ void split2(float f0, float f1, uint32_t& hi, uint32_t& lo) {
    __nv_bfloat16 h0 = __float2bfloat16(f0), h1 = __float2bfloat16(f1);
    hi = (uint32_t)__bfloat16_as_ushort(h0) | ((uint32_t)__bfloat16_as_ushort(h1) << 16);
    __nv_bfloat16 l0 = __float2bfloat16(f0 - __bfloat162float(h0));
    __nv_bfloat16 l1 = __float2bfloat16(f1 - __bfloat162float(h1));
    lo = (uint32_t)__bfloat16_as_ushort(l0) | ((uint32_t)__bfloat16_as_ushort(l1) << 16);
}

// ======================= prep / sort =======================================
__global__ void zero_kernel() {
    if (threadIdx.x < 3) { g_cnt[threadIdx.x] = 0; g_pos[threadIdx.x] = 0; }
}

__global__ void prep_s_kernel(const int* __restrict__ s_raw) {
    __shared__ int sIs64;
    if (threadIdx.x == 0) {
        int nz = 0;
        #pragma unroll
        for (int i = 1; i < 256; i += 2) nz |= s_raw[i];
        sIs64 = (nz == 0) ? 1 : 0;
    }
    __syncthreads();
    int idx = blockIdx.x * blockDim.x + threadIdx.x;
    if (idx < TOT + 512) g_perm[idx] = -1;
    if (idx < TOT) {
        int r = sIs64 ? s_raw[2 * idx] : s_raw[idx];
        g_s32[idx] = r;
        atomicAdd(&g_cnt[r], 1);
    }
}

__global__ void offsets_kernel() {
    int o1 = (g_cnt[0] + 127) & ~127;
    int o2 = o1 + ((g_cnt[1] + 127) & ~127);
    int o3 = o2 + ((g_cnt[2] + 127) & ~127);
    g_off[0] = 0; g_off[1] = o1; g_off[2] = o2; g_off[3] = o3;
    g_pos[0] = 0; g_pos[1] = o1; g_pos[2] = o2;
}

__global__ void scatter_kernel() {
    int idx = blockIdx.x * blockDim.x + threadIdx.x;
    if (idx < TOT) {
        int slot = atomicAdd(&g_pos[g_s32[idx]], 1);
        g_perm[slot] = idx;
    }
}

// Build per-relation bf16 hi/lo pre-swizzled weight images (W^T, [n][k]).
__global__ void prep_w_kernel(const float* __restrict__ W0,
                              const float* __restrict__ W1) {
    int idx = blockIdx.x * blockDim.x + threadIdx.x;   // 0..36863
    uint8_t* img = (uint8_t*)g_wimg;
    if (idx < 24576) {                 // W0: 3 relations x 8192 k-pairs
        int r = idx >> 13, p = idx & 8191;
        int k2 = p >> 7, n = p & 127;
        const float* W0r = W0 + r * 16384;
        float f0 = W0r[(2 * k2) * 128 + n];
        float f1 = W0r[(2 * k2 + 1) * 128 + n];
        uint32_t hi, lo; split2(f0, f1, hi, lo);
        uint32_t off = sw_off(n, k2 >> 2) + (k2 & 3) * 4;
        *(uint32_t*)(img + (size_t)r * 98304 + off)         = hi;
        *(uint32_t*)(img + (size_t)r * 98304 + 32768 + off) = lo;
    } else if (idx < 36864) {          // W1: 3 relations x 4096 k-pairs
        int t = idx - 24576;
        int r = t >> 12, p = t & 4095;
        int k2 = p >> 6, n = p & 63;
        const float* W1r = W1 + r * 8192;
        float f0 = W1r[(2 * k2) * 64 + n];
        float f1 = W1r[(2 * k2 + 1) * 64 + n];
        uint32_t hi, lo; split2(f0, f1, hi, lo);
        uint32_t off = sw_off(n, k2 >> 2) + (k2 & 3) * 4;
        *(uint32_t*)(img + (size_t)r * 98304 + 65536 + off) = hi;
        *(uint32_t*)(img + (size_t)r * 98304 + 81920 + off) = lo;
    }
}

// ======================= UI branch (scalar, from R1) =======================
__global__ void __launch_bounds__(256) ui_kernel(
    const float* __restrict__ u, const float* __restrict__ iv,
    const float* __restrict__ W0, const float* __restrict__ b0,
    const float* __restrict__ W1, const float* __restrict__ b1)
{
    extern __shared__ float sm[];
    float* sxT = sm;
    float* shT = sm + 128 * UI_SP;
    float* sw  = sm + 2 * 128 * UI_SP;
    float* sb  = sw + 16384;

    const int tid = threadIdx.x;
    const int rowbase = blockIdx.x * 64;

    for (int idx = tid; idx < 64 * 64; idx += 256) {
        int m = idx >> 6, d = idx & 63;
        int g = (rowbase + m) * 64 + d;
        sxT[d * UI_SP + m]        = u[g];
        sxT[(64 + d) * UI_SP + m] = iv[g];
    }
    for (int idx = tid; idx < 4096; idx += 256)
        ((float4*)sw)[idx] = ((const float4*)W0)[idx];
    if (tid < 128) sb[tid] = b0[tid];
    __syncthreads();

    for (int t = tid; t < 512; t += 256) {
        int m4 = (t >> 5) << 2, c4 = (t & 31) << 2;
        float acc[4][4] = {};
        #pragma unroll 8
        for (int k = 0; k < 128; k++) {
            float4 x4 = *(const float4*)(sxT + k * UI_SP + m4);
            float4 w4 = *(const float4*)(sw + k * 128 + c4);
            float xr[4] = {x4.x, x4.y, x4.z, x4.w};
            float wr[4] = {w4.x, w4.y, w4.z, w4.w};
            #pragma unroll
            for (int si = 0; si < 4; si++)
                #pragma unroll
                for (int ci = 0; ci < 4; ci++)
                    acc[si][ci] = fmaf(xr[si], wr[ci], acc[si][ci]);
        }
        #pragma unroll
        for (int ci = 0; ci < 4; ci++) {
            float bv = sb[c4 + ci];
            #pragma unroll
            for (int si = 0; si < 4; si++)
                shT[(c4 + ci) * UI_SP + m4 + si] = lrelu(acc[si][ci] + bv);
        }
    }
    __syncthreads();

    for (int idx = tid; idx < 2048; idx += 256)
        ((float4*)sw)[idx] = ((const float4*)W1)[idx];
    if (tid < 64) sb[tid] = b1[tid];
    __syncthreads();

    for (int t = tid; t < 256; t += 256) {
        int m4 = (t >> 4) << 2, o4 = (t & 15) << 2;
        float acc[4][4] = {};
        #pragma unroll 8
        for (int k = 0; k < 128; k++) {
            float4 x4 = *(const float4*)(shT + k * UI_SP + m4);
            float4 w4 = *(const float4*)(sw + k * 64 + o4);
            float xr[4] = {x4.x, x4.y, x4.z, x4.w};
            float wr[4] = {w4.x, w4.y, w4.z, w4.w};
            #pragma unroll
            for (int si = 0; si < 4; si++)
                #pragma unroll
                for (int ci = 0; ci < 4; ci++)
                    acc[si][ci] = fmaf(xr[si], wr[ci], acc[si][ci]);
        }
        #pragma unroll
        for (int si = 0; si < 4; si++)
            #pragma unroll
            for (int ci = 0; ci < 4; ci++)
                g_ui[(rowbase + m4 + si) * 64 + o4 + ci] =
                    lrelu(acc[si][ci] + sb[o4 + ci]);
    }
}

// ======================= AO branch (mma.sync HMMA) =========================
// smem map (bytes): 0 Xhi(32K) | 32K Xlo | 64K W0hi | 96K W0lo |
//                   128K W1hi(16K) | 144K W1lo(16K) | 160K b0(512) b1(256)
// phase2: H overwrites X region; epilogue2 D2 (128x68 f32) reuses offset 0.
#define OFF_XHI  0
#define OFF_XLO  32768
#define OFF_W    65536
#define OFF_W1   131072
#define OFF_B0   163840
#define OFF_B1   164352
#define AO_SMEM  164608

__global__ void __launch_bounds__(256) ao_mma_kernel(
    const float* __restrict__ a, const float* __restrict__ o,
    const float* __restrict__ b0, const float* __restrict__ b1,
    float* __restrict__ out)
{
    extern __shared__ char smem[];
    const uint32_t smem_base = smem_to_u32(smem);
    const int tid = threadIdx.x;
    const int lane = tid & 31;
    const int wid = tid >> 5;
    const int wm = wid & 1;        // M warp (2 x 64 rows)
    const int wn = wid >> 1;       // N warp (4 x 32 cols)
    const int slotbase = blockIdx.x * 128;

    if (slotbase >= g_off[3]) return;
    const int r = (slotbase < g_off[1]) ? 0 : (slotbase < g_off[2]) ? 1 : 2;

    float* sb0 = (float*)(smem + OFF_B0);
    float* sb1 = (float*)(smem + OFF_B1);

    // ---- weight image copy (96KB, pre-swizzled bf16) ----
    {
        const float4* wsrc = g_wimg + (size_t)r * 6144;
        float4* wdst = (float4*)(smem + OFF_W);
        #pragma unroll 4
        for (int idx = tid; idx < 6144; idx += 256) wdst[idx] = wsrc[idx];
    }
    if (tid < 128) sb0[tid] = b0[r * 128 + tid];
    if (tid < 64)  sb1[tid] = b1[r * 64 + tid];

    // ---- X gather + hi/lo split (thread = half a row) ----
    {
        const int xrow = tid >> 1;
        const int half = tid & 1;
        const int grow = g_perm[slotbase + xrow];
        const float* src = (half ? o : a);
        if (grow >= 0) {
            const float4* s4 = (const float4*)(src + (size_t)grow * 64);
            #pragma unroll
            for (int j = 0; j < 8; j++) {
                float4 v0 = s4[2 * j], v1 = s4[2 * j + 1];
                uint32_t h0, l0, h1, l1, h2, l2, h3, l3;
                split2(v0.x, v0.y, h0, l0);
                split2(v0.z, v0.w, h1, l1);
                split2(v1.x, v1.y, h2, l2);
                split2(v1.z, v1.w, h3, l3);
                uint32_t off = sw_off(xrow, half * 8 + j);
                *(uint4*)(smem + OFF_XHI + off) = make_uint4(h0, h1, h2, h3);
                *(uint4*)(smem + OFF_XLO + off) = make_uint4(l0, l1, l2, l3);
            }
        } else {
            #pragma unroll
            for (int j = 0; j < 8; j++) {
                uint32_t off = sw_off(xrow, half * 8 + j);
                *(uint4*)(smem + OFF_XHI + off) = make_uint4(0, 0, 0, 0);
                *(uint4*)(smem + OFF_XLO + off) = make_uint4(0, 0, 0, 0);
            }
        }
    }
    __syncthreads();

    // ================= GEMM1: D(128x128) over K=3x128 =================
    float acc[4][4][4];
    #pragma unroll
    for (int i = 0; i < 4; i++)
        #pragma unroll
        for (int j = 0; j < 4; j++)
            #pragma unroll
            for (int q = 0; q < 4; q++) acc[i][j][q] = 0.f;

    #pragma unroll
    for (int seg = 0; seg < 3; seg++) {
        const uint32_t Ab = smem_base + (seg == 1 ? OFF_XLO : OFF_XHI);
        const uint32_t Bb = smem_base + OFF_W + (seg == 2 ? 32768 : 0);
        #pragma unroll
        for (int kk = 0; kk < 8; kk++) {
            const int chunk = kk * 2 + (lane >> 4);
            uint32_t af[4][4];
            #pragma unroll
            for (int i = 0; i < 4; i++) {
                int row = wm * 64 + i * 16 + (lane & 15);
                ldsm_x4(af[i][0], af[i][1], af[i][2], af[i][3],
                        Ab + sw_off(row, chunk));
            }
            uint32_t bf[4][2];
            #pragma unroll
            for (int h = 0; h < 2; h++) {
                int nrow = wn * 32 + h * 16 + (lane & 7) + ((lane >> 3) & 1) * 8;
                uint32_t r0, r1, r2, r3;
                ldsm_x4(r0, r1, r2, r3, Bb + sw_off(nrow, chunk));
                bf[h * 2][0] = r0; bf[h * 2][1] = r2;
                bf[h * 2 + 1][0] = r1; bf[h * 2 + 1][1] = r3;
            }
            #pragma unroll
            for (int i = 0; i < 4; i++)
                #pragma unroll
                for (int j = 0; j < 4; j++)
                    mma_bf16(acc[i][j], af[i], bf[j][0], bf[j][1]);
        }
    }
    __syncthreads();

    // ---- epilogue1: H = lrelu(D + b0) -> bf16 hi/lo into X region ----
    #pragma unroll
    for (int i = 0; i < 4; i++) {
        int row0 = wm * 64 + i * 16 + (lane >> 2);
        #pragma unroll
        for (int j = 0; j < 4; j++) {
            int col = wn * 32 + j * 8 + 2 * (lane & 3);
            float bv0 = sb0[col], bv1 = sb0[col + 1];
            uint32_t hi0, lo0, hi1, lo1;
            split2(lrelu(acc[i][j][0] + bv0), lrelu(acc[i][j][1] + bv1), hi0, lo0);
            split2(lrelu(acc[i][j][2] + bv0), lrelu(acc[i][j][3] + bv1), hi1, lo1);
            uint32_t o0 = sw_off(row0, col >> 3) + ((2 * col) & 15);
            uint32_t o1 = sw_off(row0 + 8, col >> 3) + ((2 * col) & 15);
            *(uint32_t*)(smem + OFF_XHI + o0) = hi0;
            *(uint32_t*)(smem + OFF_XLO + o0) = lo0;
            *(uint32_t*)(smem + OFF_XHI + o1) = hi1;
            *(uint32_t*)(smem + OFF_XLO + o1) = lo1;
        }
    }
    __syncthreads();

    // ================= GEMM2: D2(128x64) over K=3x128 =================
    float acc2[4][2][4];
    #pragma unroll
    for (int i = 0; i < 4; i++)
        #pragma unroll
        for (int j = 0; j < 2; j++)
            #pragma unroll
            for (int q = 0; q < 4; q++) acc2[i][j][q] = 0.f;

    #pragma unroll
    for (int seg = 0; seg < 3; seg++) {
        const uint32_t Ab = smem_base + (seg == 1 ? OFF_XLO : OFF_XHI);
        const uint32_t Bb = smem_base + OFF_W1 + (seg == 2 ? 16384 : 0);
        #pragma unroll
        for (int kk = 0; kk < 8; kk++) {
            const int chunk = kk * 2 + (lane >> 4);
            uint32_t af[4][4];
            #pragma unroll
            for (int i = 0; i < 4; i++) {
                int row = wm * 64 + i * 16 + (lane & 15);
                ldsm_x4(af[i][0], af[i][1], af[i][2], af[i][3],
                        Ab + sw_off(row, chunk));
            }
            int nrow = wn * 16 + (lane & 7) + ((lane >> 3) & 1) * 8;
            uint32_t r0, r1, r2, r3;
            ldsm_x4(r0, r1, r2, r3, Bb + sw_off(nrow, chunk));
            #pragma unroll
            for (int i = 0; i < 4; i++) {
                mma_bf16(acc2[i][0], af[i], r0, r2);
                mma_bf16(acc2[i][1], af[i], r1, r3);
            }
        }
    }
    __syncthreads();

    // ---- epilogue2: D2 -> smem (stride 68), then bias+lrelu+dot(ui) ----
    float* sD2 = (float*)smem;
    #pragma unroll
    for (int i = 0; i < 4; i++) {
        int row0 = wm * 64 + i * 16 + (lane >> 2);
        #pragma unroll
        for (int j = 0; j < 2; j++) {
            int col = wn * 16 + j * 8 + 2 * (lane & 3);
            *(float2*)&sD2[row0 * 68 + col]       = make_float2(acc2[i][j][0], acc2[i][j][1]);
            *(float2*)&sD2[(row0 + 8) * 68 + col] = make_float2(acc2[i][j][2], acc2[i][j][3]);
        }
    }
    __syncthreads();

    if (tid < 128) {
        int grow = g_perm[slotbase + tid];
        if (grow >= 0) {
            const float4* uir = (const float4*)(g_ui + (size_t)(grow >> 5) * 64);
            const float* drow = sD2 + tid * 68;
            float s = 0.f;
            #pragma unroll
            for (int c4 = 0; c4 < 16; c4++) {
                float4 uv = uir[c4];
                float v0 = lrelu(drow[4 * c4 + 0] + sb1[4 * c4 + 0]);
                float v1 = lrelu(drow[4 * c4 + 1] + sb1[4 * c4 + 1]);
                float v2 = lrelu(drow[4 * c4 + 2] + sb1[4 * c4 + 2]);
                float v3 = lrelu(drow[4 * c4 + 3] + sb1[4 * c4 + 3]);
                s = fmaf(v0, uv.x, s); s = fmaf(v1, uv.y, s);
                s = fmaf(v2, uv.z, s); s = fmaf(v3, uv.w, s);
            }
            out[grow] = s;
        }
    }
}

// ===========================================================================
extern "C" void kernel_launch(void* const* d_in, const int* in_sizes, int n_in,
                              void* d_out, int out_size) {
    const float* u    = (const float*)d_in[0];
    const float* iv   = (const float*)d_in[1];
    const float* a    = (const float*)d_in[2];
    const float* o    = (const float*)d_in[3];
    const int*   s    = (const int*)  d_in[4];
    const float* aoW0 = (const float*)d_in[5];
    const float* aob0 = (const float*)d_in[6];
    const float* aoW1 = (const float*)d_in[7];
    const float* aob1 = (const float*)d_in[8];
    const float* uiW0 = (const float*)d_in[9];
    const float* uib0 = (const float*)d_in[10];
    const float* uiW1 = (const float*)d_in[11];
    const float* uib1 = (const float*)d_in[12];
    float* out = (float*)d_out;

    const size_t ui_smem = (size_t)(128 * UI_SP * 2 + 16384 + 128) * sizeof(float);
    cudaFuncSetAttribute((const void*)ui_kernel,
                         cudaFuncAttributeMaxDynamicSharedMemorySize, (int)ui_smem);
    cudaFuncSetAttribute((const void*)ao_mma_kernel,
                         cudaFuncAttributeMaxDynamicSharedMemorySize, AO_SMEM);

    zero_kernel<<<1, 32>>>();
    prep_s_kernel<<<(TOT + 512 + 255) / 256, 256>>>(s);
    prep_w_kernel<<<144, 256>>>(aoW0, aoW1);
    offsets_kernel<<<1, 1>>>();
    scatter_kernel<<<TOT / 256, 256>>>();
    ui_kernel<<<B_ / 64, 256, ui_smem>>>(u, iv, uiW0, uib0, uiW1, uib1);
    ao_mma_kernel<<<NCTA_AO, 256, AO_SMEM>>>(a, o, aob0, aob1, out);
}

// round 5
// speedup vs baseline: 2.1878x; 1.2011x over previous
#include <cuda_runtime.h>
#include <cuda_fp16.h>
#include <cstdint>

// Model_53283364274775 on GB300 (plain sm_103 PTX target -> no tcgen05):
// AO branch via warp-level mma.sync fp16 HMMA, 2-term activation split
// (X = Xhi + Xlo, weights fp16-hi only), fp32 accumulate.
// Global relation counting-sort -> relation-uniform 128-row CTAs, 2 CTAs/SM.

#define B_   8192
#define N_   32
#define TOT  (B_ * N_)
#define SLOPE 0.01f
#define UI_SP 68
#define NCTA_AO 2051

__device__ int   g_s32[TOT];
__device__ int   g_cnt[3];
__device__ int   g_pos[3];
__device__ int   g_off[4];
__device__ int   g_perm[TOT + 512];
__device__ float g_ui[B_ * 64];
// Per-relation prebuilt weight image (pre-swizzled fp16 W^T):
// [0,32K) W0hi  [32K,48K) W1hi ; 48KB per relation
__device__ float4 g_wimg[3 * 3072];

__device__ __forceinline__ float lrelu(float x) { return x >= 0.f ? x : SLOPE * x; }

__device__ __forceinline__ uint32_t smem_to_u32(const void* p) {
    uint32_t a;
    asm("{ .reg .u64 t; cvta.to.shared.u64 t, %1; cvt.u32.u64 %0, t; }"
        : "=r"(a) : "l"(p));
    return a;
}
__device__ __forceinline__ void ldsm_x4(uint32_t& r0, uint32_t& r1,
                                        uint32_t& r2, uint32_t& r3, uint32_t addr) {
    asm volatile("ldmatrix.sync.aligned.m8n8.x4.shared.b16 {%0,%1,%2,%3}, [%4];"
        : "=r"(r0), "=r"(r1), "=r"(r2), "=r"(r3) : "r"(addr));
}
__device__ __forceinline__ void mma_f16(float* d, const uint32_t* a4,
                                        uint32_t b0, uint32_t b1) {
    asm volatile("mma.sync.aligned.m16n8k16.row.col.f32.f16.f16.f32 "
        "{%0,%1,%2,%3}, {%4,%5,%6,%7}, {%8,%9}, {%0,%1,%2,%3};"
        : "+f"(d[0]), "+f"(d[1]), "+f"(d[2]), "+f"(d[3])
        : "r"(a4[0]), "r"(a4[1]), "r"(a4[2]), "r"(a4[3]), "r"(b0), "r"(b1));
}
// 256B rows of fp16, XOR swizzle on 16B chunks: conflict-free ldmatrix
__device__ __forceinline__ uint32_t sw_off(int row, int chunk16) {
    return (uint32_t)(row * 256 + ((chunk16 ^ (row & 7)) << 4));
}
// pack (f0,f1) -> fp16 hi pair + fp16 residual lo pair
__device__ __forceinline__ void split2h(float f0, float f1, uint32_t& hi, uint32_t& lo) {
    __half h0 = __float2half_rn(f0), h1 = __float2half_rn(f1);
    hi = (uint32_t)__half_as_ushort(h0) | ((uint32_t)__half_as_ushort(h1) << 16);
    __half l0 = __float2half_rn(f0 - __half2float(h0));
    __half l1 = __float2half_rn(f1 - __half2float(h1));
    lo = (uint32_t)__half_as_ushort(l0) | ((uint32_t)__half_as_ushort(l1) << 16);
}
// fp16 hi only (for weights)
__device__ __forceinline__ uint32_t pack2h(float f0, float f1) {
    return (uint32_t)__half_as_ushort(__float2half_rn(f0)) |
           ((uint32_t)__half_as_ushort(__float2half_rn(f1)) << 16);
}

// ======================= prep / sort =======================================
__global__ void zero_kernel() {
    if (threadIdx.x < 3) { g_cnt[threadIdx.x] = 0; g_pos[threadIdx.x] = 0; }
}

__global__ void prep_s_kernel(const int* __restrict__ s_raw) {
    __shared__ int sIs64;
    if (threadIdx.x == 0) {
        int nz = 0;
        #pragma unroll
        for (int i = 1; i < 256; i += 2) nz |= s_raw[i];
        sIs64 = (nz == 0) ? 1 : 0;
    }
    __syncthreads();
    int idx = blockIdx.x * blockDim.x + threadIdx.x;
    if (idx < TOT + 512) g_perm[idx] = -1;
    if (idx < TOT) {
        int r = sIs64 ? s_raw[2 * idx] : s_raw[idx];
        g_s32[idx] = r;
        atomicAdd(&g_cnt[r], 1);
    }
}

__global__ void offsets_kernel() {
    int o1 = (g_cnt[0] + 127) & ~127;
    int o2 = o1 + ((g_cnt[1] + 127) & ~127);
    int o3 = o2 + ((g_cnt[2] + 127) & ~127);
    g_off[0] = 0; g_off[1] = o1; g_off[2] = o2; g_off[3] = o3;
    g_pos[0] = 0; g_pos[1] = o1; g_pos[2] = o2;
}

__global__ void scatter_kernel() {
    int idx = blockIdx.x * blockDim.x + threadIdx.x;
    if (idx < TOT) {
        int slot = atomicAdd(&g_pos[g_s32[idx]], 1);
        g_perm[slot] = idx;
    }
}

// Build per-relation fp16 pre-swizzled weight images (W^T, [n][k]).
__global__ void prep_w_kernel(const float* __restrict__ W0,
                              const float* __restrict__ W1) {
    int idx = blockIdx.x * blockDim.x + threadIdx.x;   // 0..36863
    uint8_t* img = (uint8_t*)g_wimg;
    if (idx < 24576) {                 // W0: 3 relations x 8192 (k-pair, n)
        int r = idx >> 13, p = idx & 8191;
        int k2 = p >> 7, n = p & 127;
        const float* W0r = W0 + r * 16384;
        uint32_t hi = pack2h(W0r[(2 * k2) * 128 + n], W0r[(2 * k2 + 1) * 128 + n]);
        uint32_t off = sw_off(n, k2 >> 2) + (k2 & 3) * 4;
        *(uint32_t*)(img + (size_t)r * 49152 + off) = hi;
    } else if (idx < 36864) {          // W1: 3 relations x 4096
        int t = idx - 24576;
        int r = t >> 12, p = t & 4095;
        int k2 = p >> 6, n = p & 63;
        const float* W1r = W1 + r * 8192;
        uint32_t hi = pack2h(W1r[(2 * k2) * 64 + n], W1r[(2 * k2 + 1) * 64 + n]);
        uint32_t off = sw_off(n, k2 >> 2) + (k2 & 3) * 4;
        *(uint32_t*)(img + (size_t)r * 49152 + 32768 + off) = hi;
    }
}

// ======================= UI branch (scalar, from R1) =======================
__global__ void __launch_bounds__(256) ui_kernel(
    const float* __restrict__ u, const float* __restrict__ iv,
    const float* __restrict__ W0, const float* __restrict__ b0,
    const float* __restrict__ W1, const float* __restrict__ b1)
{
    extern __shared__ float sm[];
    float* sxT = sm;
    float* shT = sm + 128 * UI_SP;
    float* sw  = sm + 2 * 128 * UI_SP;
    float* sb  = sw + 16384;

    const int tid = threadIdx.x;
    const int rowbase = blockIdx.x * 64;

    for (int idx = tid; idx < 64 * 64; idx += 256) {
        int m = idx >> 6, d = idx & 63;
        int g = (rowbase + m) * 64 + d;
        sxT[d * UI_SP + m]        = u[g];
        sxT[(64 + d) * UI_SP + m] = iv[g];
    }
    for (int idx = tid; idx < 4096; idx += 256)
        ((float4*)sw)[idx] = ((const float4*)W0)[idx];
    if (tid < 128) sb[tid] = b0[tid];
    __syncthreads();

    for (int t = tid; t < 512; t += 256) {
        int m4 = (t >> 5) << 2, c4 = (t & 31) << 2;
        float acc[4][4] = {};
        #pragma unroll 8
        for (int k = 0; k < 128; k++) {
            float4 x4 = *(const float4*)(sxT + k * UI_SP + m4);
            float4 w4 = *(const float4*)(sw + k * 128 + c4);
            float xr[4] = {x4.x, x4.y, x4.z, x4.w};
            float wr[4] = {w4.x, w4.y, w4.z, w4.w};
            #pragma unroll
            for (int si = 0; si < 4; si++)
                #pragma unroll
                for (int ci = 0; ci < 4; ci++)
                    acc[si][ci] = fmaf(xr[si], wr[ci], acc[si][ci]);
        }
        #pragma unroll
        for (int ci = 0; ci < 4; ci++) {
            float bv = sb[c4 + ci];
            #pragma unroll
            for (int si = 0; si < 4; si++)
                shT[(c4 + ci) * UI_SP + m4 + si] = lrelu(acc[si][ci] + bv);
        }
    }
    __syncthreads();

    for (int idx = tid; idx < 2048; idx += 256)
        ((float4*)sw)[idx] = ((const float4*)W1)[idx];
    if (tid < 64) sb[tid] = b1[tid];
    __syncthreads();

    for (int t = tid; t < 256; t += 256) {
        int m4 = (t >> 4) << 2, o4 = (t & 15) << 2;
        float acc[4][4] = {};
        #pragma unroll 8
        for (int k = 0; k < 128; k++) {
            float4 x4 = *(const float4*)(shT + k * UI_SP + m4);
            float4 w4 = *(const float4*)(sw + k * 64 + o4);
            float xr[4] = {x4.x, x4.y, x4.z, x4.w};
            float wr[4] = {w4.x, w4.y, w4.z, w4.w};
            #pragma unroll
            for (int si = 0; si < 4; si++)
                #pragma unroll
                for (int ci = 0; ci < 4; ci++)
                    acc[si][ci] = fmaf(xr[si], wr[ci], acc[si][ci]);
        }
        #pragma unroll
        for (int si = 0; si < 4; si++)
            #pragma unroll
            for (int ci = 0; ci < 4; ci++)
                g_ui[(rowbase + m4 + si) * 64 + o4 + ci] =
                    lrelu(acc[si][ci] + sb[o4 + ci]);
    }
}

// ======================= AO branch (mma.sync fp16) =========================
// smem map (bytes): 0 Xhi(32K) | 32K Xlo(32K) | 64K W0hi(32K) | 96K W1hi(16K)
//                   | 112K b0(512) b1(256).  Total 115456 -> 2 CTAs/SM.
// phase2: H (hi/lo) overwrites X region; epilogue2 D2 (128x68 f32 = 34KB)
// reuses [0,64K) after GEMM2.
#define OFF_XHI  0
#define OFF_XLO  32768
#define OFF_W0   65536
#define OFF_W1   98304
#define OFF_B0   114688
#define OFF_B1   115200
#define AO_SMEM  115456

__global__ void __launch_bounds__(256, 2) ao_mma_kernel(
    const float* __restrict__ a, const float* __restrict__ o,
    const float* __restrict__ b0, const float* __restrict__ b1,
    float* __restrict__ out)
{
    extern __shared__ char smem[];
    const uint32_t smem_base = smem_to_u32(smem);
    const int tid = threadIdx.x;
    const int lane = tid & 31;
    const int wid = tid >> 5;
    const int wm = wid & 1;        // M warp (2 x 64 rows)
    const int wn = wid >> 1;       // N warp (4 x 32 cols)
    const int slotbase = blockIdx.x * 128;

    if (slotbase >= g_off[3]) return;
    const int r = (slotbase < g_off[1]) ? 0 : (slotbase < g_off[2]) ? 1 : 2;

    float* sb0 = (float*)(smem + OFF_B0);
    float* sb1 = (float*)(smem + OFF_B1);

    // ---- weight image copy (48KB, pre-swizzled fp16) ----
    {
        const float4* wsrc = g_wimg + (size_t)r * 3072;
        float4* wdst = (float4*)(smem + OFF_W0);
        #pragma unroll 4
        for (int idx = tid; idx < 3072; idx += 256) wdst[idx] = wsrc[idx];
    }
    if (tid < 128) sb0[tid] = b0[r * 128 + tid];
    if (tid < 64)  sb1[tid] = b1[r * 64 + tid];

    // ---- X gather + hi/lo split (thread = half a row) ----
    {
        const int xrow = tid >> 1;
        const int half = tid & 1;
        const int grow = g_perm[slotbase + xrow];
        const float* src = (half ? o : a);
        if (grow >= 0) {
            const float4* s4 = (const float4*)(src + (size_t)grow * 64);
            #pragma unroll
            for (int j = 0; j < 8; j++) {
                float4 v0 = s4[2 * j], v1 = s4[2 * j + 1];
                uint32_t h0, l0, h1, l1, h2, l2, h3, l3;
                split2h(v0.x, v0.y, h0, l0);
                split2h(v0.z, v0.w, h1, l1);
                split2h(v1.x, v1.y, h2, l2);
                split2h(v1.z, v1.w, h3, l3);
                uint32_t off = sw_off(xrow, half * 8 + j);
                *(uint4*)(smem + OFF_XHI + off) = make_uint4(h0, h1, h2, h3);
                *(uint4*)(smem + OFF_XLO + off) = make_uint4(l0, l1, l2, l3);
            }
        } else {
            #pragma unroll
            for (int j = 0; j < 8; j++) {
                uint32_t off = sw_off(xrow, half * 8 + j);
                *(uint4*)(smem + OFF_XHI + off) = make_uint4(0, 0, 0, 0);
                *(uint4*)(smem + OFF_XLO + off) = make_uint4(0, 0, 0, 0);
            }
        }
    }
    __syncthreads();

    // ================= GEMM1: D(128x128) over K=2x128 =================
    float acc[4][4][4];
    #pragma unroll
    for (int i = 0; i < 4; i++)
        #pragma unroll
        for (int j = 0; j < 4; j++)
            #pragma unroll
            for (int q = 0; q < 4; q++) acc[i][j][q] = 0.f;

    #pragma unroll
    for (int seg = 0; seg < 2; seg++) {
        const uint32_t Ab = smem_base + (seg ? OFF_XLO : OFF_XHI);
        const uint32_t Bb = smem_base + OFF_W0;
        #pragma unroll
        for (int kk = 0; kk < 8; kk++) {
            const int chunk = kk * 2 + (lane >> 4);
            uint32_t af[4][4];
            #pragma unroll
            for (int i = 0; i < 4; i++) {
                int row = wm * 64 + i * 16 + (lane & 15);
                ldsm_x4(af[i][0], af[i][1], af[i][2], af[i][3],
                        Ab + sw_off(row, chunk));
            }
            uint32_t bf[4][2];
            #pragma unroll
            for (int h = 0; h < 2; h++) {
                int nrow = wn * 32 + h * 16 + (lane & 7) + ((lane >> 3) & 1) * 8;
                uint32_t r0, r1, r2, r3;
                ldsm_x4(r0, r1, r2, r3, Bb + sw_off(nrow, chunk));
                bf[h * 2][0] = r0; bf[h * 2][1] = r2;
                bf[h * 2 + 1][0] = r1; bf[h * 2 + 1][1] = r3;
            }
            #pragma unroll
            for (int i = 0; i < 4; i++)
                #pragma unroll
                for (int j = 0; j < 4; j++)
                    mma_f16(acc[i][j], af[i], bf[j][0], bf[j][1]);
        }
    }
    __syncthreads();

    // ---- epilogue1: H = lrelu(D + b0) -> fp16 hi/lo into X region ----
    #pragma unroll
    for (int i = 0; i < 4; i++) {
        int row0 = wm * 64 + i * 16 + (lane >> 2);
        #pragma unroll
        for (int j = 0; j < 4; j++) {
            int col = wn * 32 + j * 8 + 2 * (lane & 3);
            float bv0 = sb0[col], bv1 = sb0[col + 1];
            uint32_t hi0, lo0, hi1, lo1;
            split2h(lrelu(acc[i][j][0] + bv0), lrelu(acc[i][j][1] + bv1), hi0, lo0);
            split2h(lrelu(acc[i][j][2] + bv0), lrelu(acc[i][j][3] + bv1), hi1, lo1);
            uint32_t o0 = sw_off(row0, col >> 3) + ((2 * col) & 15);
            uint32_t o1 = sw_off(row0 + 8, col >> 3) + ((2 * col) & 15);
            *(uint32_t*)(smem + OFF_XHI + o0) = hi0;
            *(uint32_t*)(smem + OFF_XLO + o0) = lo0;
            *(uint32_t*)(smem + OFF_XHI + o1) = hi1;
            *(uint32_t*)(smem + OFF_XLO + o1) = lo1;
        }
    }
    __syncthreads();

    // ================= GEMM2: D2(128x64) over K=2x128 =================
    float acc2[4][2][4];
    #pragma unroll
    for (int i = 0; i < 4; i++)
        #pragma unroll
        for (int j = 0; j < 2; j++)
            #pragma unroll
            for (int q = 0; q < 4; q++) acc2[i][j][q] = 0.f;

    #pragma unroll
    for (int seg = 0; seg < 2; seg++) {
        const uint32_t Ab = smem_base + (seg ? OFF_XLO : OFF_XHI);
        const uint32_t Bb = smem_base + OFF_W1;
        #pragma unroll
        for (int kk = 0; kk < 8; kk++) {
            const int chunk = kk * 2 + (lane >> 4);
            uint32_t af[4][4];
            #pragma unroll
            for (int i = 0; i < 4; i++) {
                int row = wm * 64 + i * 16 + (lane & 15);
                ldsm_x4(af[i][0], af[i][1], af[i][2], af[i][3],
                        Ab + sw_off(row, chunk));
            }
            int nrow = wn * 16 + (lane & 7) + ((lane >> 3) & 1) * 8;
            uint32_t r0, r1, r2, r3;
            ldsm_x4(r0, r1, r2, r3, Bb + sw_off(nrow, chunk));
            #pragma unroll
            for (int i = 0; i < 4; i++) {
                mma_f16(acc2[i][0], af[i], r0, r2);
                mma_f16(acc2[i][1], af[i], r1, r3);
            }
        }
    }
    __syncthreads();

    // ---- epilogue2: D2 -> smem (stride 68), then bias+lrelu+dot(ui) ----
    float* sD2 = (float*)smem;
    #pragma unroll
    for (int i = 0; i < 4; i++) {
        int row0 = wm * 64 + i * 16 + (lane >> 2);
        #pragma unroll
        for (int j = 0; j < 2; j++) {
            int col = wn * 16 + j * 8 + 2 * (lane & 3);
            *(float2*)&sD2[row0 * 68 + col]       = make_float2(acc2[i][j][0], acc2[i][j][1]);
            *(float2*)&sD2[(row0 + 8) * 68 + col] = make_float2(acc2[i][j][2], acc2[i][j][3]);
        }
    }
    __syncthreads();

    if (tid < 128) {
        int grow = g_perm[slotbase + tid];
        if (grow >= 0) {
            const float4* uir = (const float4*)(g_ui + (size_t)(grow >> 5) * 64);
            const float* drow = sD2 + tid * 68;
            float s = 0.f;
            #pragma unroll
            for (int c4 = 0; c4 < 16; c4++) {
                float4 uv = uir[c4];
                float v0 = lrelu(drow[4 * c4 + 0] + sb1[4 * c4 + 0]);
                float v1 = lrelu(drow[4 * c4 + 1] + sb1[4 * c4 + 1]);
                float v2 = lrelu(drow[4 * c4 + 2] + sb1[4 * c4 + 2]);
                float v3 = lrelu(drow[4 * c4 + 3] + sb1[4 * c4 + 3]);
                s = fmaf(v0, uv.x, s); s = fmaf(v1, uv.y, s);
                s = fmaf(v2, uv.z, s); s = fmaf(v3, uv.w, s);
            }
            out[grow] = s;
        }
    }
}

// ===========================================================================
extern "C" void kernel_launch(void* const* d_in, const int* in_sizes, int n_in,
                              void* d_out, int out_size) {
    const float* u    = (const float*)d_in[0];
    const float* iv   = (const float*)d_in[1];
    const float* a    = (const float*)d_in[2];
    const float* o    = (const float*)d_in[3];
    const int*   s    = (const int*)  d_in[4];
    const float* aoW0 = (const float*)d_in[5];
    const float* aob0 = (const float*)d_in[6];
    const float* aoW1 = (const float*)d_in[7];
    const float* aob1 = (const float*)d_in[8];
    const float* uiW0 = (const float*)d_in[9];
    const float* uib0 = (const float*)d_in[10];
    const float* uiW1 = (const float*)d_in[11];
    const float* uib1 = (const float*)d_in[12];
    float* out = (float*)d_out;

    const size_t ui_smem = (size_t)(128 * UI_SP * 2 + 16384 + 128) * sizeof(float);
    cudaFuncSetAttribute((const void*)ui_kernel,
                         cudaFuncAttributeMaxDynamicSharedMemorySize, (int)ui_smem);
    cudaFuncSetAttribute((const void*)ao_mma_kernel,
                         cudaFuncAttributeMaxDynamicSharedMemorySize, AO_SMEM);

    zero_kernel<<<1, 32>>>();
    prep_s_kernel<<<(TOT + 512 + 255) / 256, 256>>>(s);
    prep_w_kernel<<<144, 256>>>(aoW0, aoW1);
    offsets_kernel<<<1, 1>>>();
    scatter_kernel<<<TOT / 256, 256>>>();
    ui_kernel<<<B_ / 64, 256, ui_smem>>>(u, iv, uiW0, uib0, uiW1, uib1);
    ao_mma_kernel<<<NCTA_AO, 256, AO_SMEM>>>(a, o, aob0, aob1, out);
}

// round 6
// speedup vs baseline: 3.7577x; 1.7176x over previous
#include <cuda_runtime.h>
#include <cuda_fp16.h>
#include <cstdint>

// Model_53283364274775 on GB300 (plain sm_103 PTX target -> no tcgen05):
// single-pass fp16 mma.sync for both AO (relation-sorted) and UI branches,
// fp32 accumulate. Fixed-base bucket sort (no offsets pass), 5 launches.

#define B_   8192
#define N_   32
#define TOT  (B_ * N_)          // 262144 = 2^18
#define SLOPE 0.01f

__device__ int   g_pos[3];
__device__ int   g_perm[3 * TOT];
__device__ float g_ui[B_ * 64];
// Prebuilt pre-swizzled fp16 W^T images: relations 0..2 = AO, 3 = UI.
// Per relation: [0,32K) W0, [32K,48K) W1. 48KB each.
__device__ float4 g_wimg[4 * 3072];

__device__ __forceinline__ float lrelu(float x) { return x >= 0.f ? x : SLOPE * x; }

__device__ __forceinline__ uint32_t smem_to_u32(const void* p) {
    uint32_t a;
    asm("{ .reg .u64 t; cvta.to.shared.u64 t, %1; cvt.u32.u64 %0, t; }"
        : "=r"(a) : "l"(p));
    return a;
}
__device__ __forceinline__ void ldsm_x4(uint32_t& r0, uint32_t& r1,
                                        uint32_t& r2, uint32_t& r3, uint32_t addr) {
    asm volatile("ldmatrix.sync.aligned.m8n8.x4.shared.b16 {%0,%1,%2,%3}, [%4];"
        : "=r"(r0), "=r"(r1), "=r"(r2), "=r"(r3) : "r"(addr));
}
__device__ __forceinline__ void mma_f16(float* d, const uint32_t* a4,
                                        uint32_t b0, uint32_t b1) {
    asm volatile("mma.sync.aligned.m16n8k16.row.col.f32.f16.f16.f32 "
        "{%0,%1,%2,%3}, {%4,%5,%6,%7}, {%8,%9}, {%0,%1,%2,%3};"
        : "+f"(d[0]), "+f"(d[1]), "+f"(d[2]), "+f"(d[3])
        : "r"(a4[0]), "r"(a4[1]), "r"(a4[2]), "r"(a4[3]), "r"(b0), "r"(b1));
}
// 256B rows of fp16, XOR swizzle on 16B chunks: conflict-free ldmatrix
__device__ __forceinline__ uint32_t sw_off(int row, int chunk16) {
    return (uint32_t)(row * 256 + ((chunk16 ^ (row & 7)) << 4));
}
__device__ __forceinline__ uint32_t pack2h(float f0, float f1) {
    return (uint32_t)__half_as_ushort(__float2half_rn(f0)) |
           ((uint32_t)__half_as_ushort(__float2half_rn(f1)) << 16);
}

// ======================= prep =============================================
__global__ void init_kernel() {
    if (threadIdx.x < 3) g_pos[threadIdx.x] = threadIdx.x * TOT;
}

// bucket-scatter with inline int64/int32 sniff (odd words of first 256 ints
// are all zero iff little-endian int64 with values 0..2)
__global__ void scatter_kernel(const int* __restrict__ s_raw) {
    __shared__ int sIs64;
    if (threadIdx.x == 0) {
        int nz = 0;
        #pragma unroll
        for (int i = 1; i < 256; i += 2) nz |= s_raw[i];
        sIs64 = (nz == 0) ? 1 : 0;
    }
    __syncthreads();
    int idx = blockIdx.x * blockDim.x + threadIdx.x;
    if (idx < TOT) {
        int r = sIs64 ? s_raw[2 * idx] : s_raw[idx];
        int slot = atomicAdd(&g_pos[r], 1);
        g_perm[slot] = idx;
    }
}

// Build pre-swizzled fp16 W^T images for relations 0..2 (AO) and 3 (UI).
__global__ void prep_w_kernel(const float* __restrict__ aoW0,
                              const float* __restrict__ aoW1,
                              const float* __restrict__ uiW0,
                              const float* __restrict__ uiW1) {
    int idx = blockIdx.x * blockDim.x + threadIdx.x;   // 0..49151
    uint8_t* img = (uint8_t*)g_wimg;
    if (idx < 32768) {                 // W0: 4 relations x 8192 (k-pair, n)
        int r = idx >> 13, p = idx & 8191;
        int k2 = p >> 7, n = p & 127;
        const float* W = (r < 3) ? (aoW0 + r * 16384) : uiW0;
        uint32_t hi = pack2h(W[(2 * k2) * 128 + n], W[(2 * k2 + 1) * 128 + n]);
        uint32_t off = sw_off(n, k2 >> 2) + (k2 & 3) * 4;
        *(uint32_t*)(img + (size_t)r * 49152 + off) = hi;
    } else if (idx < 49152) {          // W1: 4 relations x 4096
        int t = idx - 32768;
        int r = t >> 12, p = t & 4095;
        int k2 = p >> 6, n = p & 63;
        const float* W = (r < 3) ? (aoW1 + r * 8192) : uiW1;
        uint32_t hi = pack2h(W[(2 * k2) * 64 + n], W[(2 * k2 + 1) * 64 + n]);
        uint32_t off = sw_off(n, k2 >> 2) + (k2 & 3) * 4;
        *(uint32_t*)(img + (size_t)r * 49152 + 32768 + off) = hi;
    }
}

// ======================= shared mma machinery ==============================
// smem map (bytes): 0 X(32K) | 32K W0(32K) | 64K W1(16K) | 80K b0(512) b1(256)
#define OFF_X    0
#define OFF_W0   32768
#define OFF_W1   65536
#define OFF_B0   81920
#define OFF_B1   82432
#define MM_SMEM  82688

// GEMM1: D(128x128) = X(128x128) @ W0^T, then H=lrelu(D+b0) back into X.
// GEMM2: acc2 = H(128x128) @ W1^T (128x64). Caller does epilogue2.
__device__ __forceinline__ void two_layer_mma(
    char* smem, uint32_t smem_base, int tid, int lane, int wm, int wn,
    float (&acc2)[4][2][4])
{
    const float* sb0 = (const float*)(smem + OFF_B0);

    // ---- GEMM1 ----
    float acc[4][4][4];
    #pragma unroll
    for (int i = 0; i < 4; i++)
        #pragma unroll
        for (int j = 0; j < 4; j++)
            #pragma unroll
            for (int q = 0; q < 4; q++) acc[i][j][q] = 0.f;

    {
        const uint32_t Ab = smem_base + OFF_X;
        const uint32_t Bb = smem_base + OFF_W0;
        #pragma unroll
        for (int kk = 0; kk < 8; kk++) {
            const int chunk = kk * 2 + (lane >> 4);
            uint32_t af[4][4];
            #pragma unroll
            for (int i = 0; i < 4; i++) {
                int row = wm * 64 + i * 16 + (lane & 15);
                ldsm_x4(af[i][0], af[i][1], af[i][2], af[i][3],
                        Ab + sw_off(row, chunk));
            }
            uint32_t bf[4][2];
            #pragma unroll
            for (int h = 0; h < 2; h++) {
                int nrow = wn * 32 + h * 16 + (lane & 7) + ((lane >> 3) & 1) * 8;
                uint32_t r0, r1, r2, r3;
                ldsm_x4(r0, r1, r2, r3, Bb + sw_off(nrow, chunk));
                bf[h * 2][0] = r0; bf[h * 2][1] = r2;
                bf[h * 2 + 1][0] = r1; bf[h * 2 + 1][1] = r3;
            }
            #pragma unroll
            for (int i = 0; i < 4; i++)
                #pragma unroll
                for (int j = 0; j < 4; j++)
                    mma_f16(acc[i][j], af[i], bf[j][0], bf[j][1]);
        }
    }
    __syncthreads();

    // ---- epilogue1: H = lrelu(D + b0) -> fp16 into X region ----
    #pragma unroll
    for (int i = 0; i < 4; i++) {
        int row0 = wm * 64 + i * 16 + (lane >> 2);
        #pragma unroll
        for (int j = 0; j < 4; j++) {
            int col = wn * 32 + j * 8 + 2 * (lane & 3);
            float bv0 = sb0[col], bv1 = sb0[col + 1];
            uint32_t h0 = pack2h(lrelu(acc[i][j][0] + bv0), lrelu(acc[i][j][1] + bv1));
            uint32_t h1 = pack2h(lrelu(acc[i][j][2] + bv0), lrelu(acc[i][j][3] + bv1));
            uint32_t o0 = sw_off(row0, col >> 3) + ((2 * col) & 15);
            uint32_t o1 = sw_off(row0 + 8, col >> 3) + ((2 * col) & 15);
            *(uint32_t*)(smem + OFF_X + o0) = h0;
            *(uint32_t*)(smem + OFF_X + o1) = h1;
        }
    }
    __syncthreads();

    // ---- GEMM2 ----
    #pragma unroll
    for (int i = 0; i < 4; i++)
        #pragma unroll
        for (int j = 0; j < 2; j++)
            #pragma unroll
            for (int q = 0; q < 4; q++) acc2[i][j][q] = 0.f;

    {
        const uint32_t Ab = smem_base + OFF_X;
        const uint32_t Bb = smem_base + OFF_W1;
        #pragma unroll
        for (int kk = 0; kk < 8; kk++) {
            const int chunk = kk * 2 + (lane >> 4);
            uint32_t af[4][4];
            #pragma unroll
            for (int i = 0; i < 4; i++) {
                int row = wm * 64 + i * 16 + (lane & 15);
                ldsm_x4(af[i][0], af[i][1], af[i][2], af[i][3],
                        Ab + sw_off(row, chunk));
            }
            int nrow = wn * 16 + (lane & 7) + ((lane >> 3) & 1) * 8;
            uint32_t r0, r1, r2, r3;
            ldsm_x4(r0, r1, r2, r3, Bb + sw_off(nrow, chunk));
            #pragma unroll
            for (int i = 0; i < 4; i++) {
                mma_f16(acc2[i][0], af[i], r0, r2);
                mma_f16(acc2[i][1], af[i], r1, r3);
            }
        }
    }
}

__device__ __forceinline__ void load_weights(char* smem, int r, int tid,
                                             const float* b0, const float* b1) {
    const float4* wsrc = g_wimg + (size_t)r * 3072;
    float4* wdst = (float4*)(smem + OFF_W0);
    #pragma unroll 4
    for (int idx = tid; idx < 3072; idx += 256) wdst[idx] = wsrc[idx];
    if (tid < 128) ((float*)(smem + OFF_B0))[tid] = b0[tid];
    if (tid < 64)  ((float*)(smem + OFF_B1))[tid] = b1[tid];
}

// ======================= UI branch (mma) ===================================
__global__ void __launch_bounds__(256, 2) ui_mma_kernel(
    const float* __restrict__ u, const float* __restrict__ iv,
    const float* __restrict__ b0, const float* __restrict__ b1)
{
    extern __shared__ char smem[];
    const uint32_t smem_base = smem_to_u32(smem);
    const int tid = threadIdx.x;
    const int lane = tid & 31;
    const int wm = (tid >> 5) & 1;
    const int wn = tid >> 6;
    const int rowbase = blockIdx.x * 128;

    load_weights(smem, 3, tid, b0, b1);

    // X gather: thread = half a row; half 0 = u (k 0..63), half 1 = i
    {
        const int xrow = tid >> 1;
        const int half = tid & 1;
        const float* src = (half ? iv : u) + (size_t)(rowbase + xrow) * 64;
        #pragma unroll
        for (int j = 0; j < 8; j++) {
            float4 v0 = ((const float4*)src)[2 * j];
            float4 v1 = ((const float4*)src)[2 * j + 1];
            uint32_t off = sw_off(xrow, half * 8 + j);
            *(uint4*)(smem + OFF_X + off) = make_uint4(
                pack2h(v0.x, v0.y), pack2h(v0.z, v0.w),
                pack2h(v1.x, v1.y), pack2h(v1.z, v1.w));
        }
    }
    __syncthreads();

    float acc2[4][2][4];
    two_layer_mma(smem, smem_base, tid, lane, wm, wn, acc2);

    // epilogue: g_ui = lrelu(D2 + b1) straight from fragments
    const float* sb1 = (const float*)(smem + OFF_B1);
    #pragma unroll
    for (int i = 0; i < 4; i++) {
        int row0 = wm * 64 + i * 16 + (lane >> 2);
        #pragma unroll
        for (int j = 0; j < 2; j++) {
            int col = wn * 16 + j * 8 + 2 * (lane & 3);
            float bv0 = sb1[col], bv1 = sb1[col + 1];
            *(float2*)&g_ui[(size_t)(rowbase + row0) * 64 + col] =
                make_float2(lrelu(acc2[i][j][0] + bv0), lrelu(acc2[i][j][1] + bv1));
            *(float2*)&g_ui[(size_t)(rowbase + row0 + 8) * 64 + col] =
                make_float2(lrelu(acc2[i][j][2] + bv0), lrelu(acc2[i][j][3] + bv1));
        }
    }
}

// ======================= AO branch (mma) ===================================
__global__ void __launch_bounds__(256, 2) ao_mma_kernel(
    const float* __restrict__ a, const float* __restrict__ o,
    const float* __restrict__ b0, const float* __restrict__ b1,
    float* __restrict__ out)
{
    extern __shared__ char smem[];
    const uint32_t smem_base = smem_to_u32(smem);
    const int tid = threadIdx.x;
    const int lane = tid & 31;
    const int wm = (tid >> 5) & 1;
    const int wn = tid >> 6;
    const int slotbase = blockIdx.x * 128;      // absolute in [0, 3*TOT)
    const int r = slotbase >> 18;               // TOT = 2^18
    const int local = slotbase & (TOT - 1);
    const int count = g_pos[r] - r * TOT;
    if (local >= count) return;                 // empty tail CTA
    const int nvalid = min(128, count - local);

    load_weights(smem, r, tid, b0 + r * 128, b1 + r * 64);

    // X gather: thread = half a row; half 0 = a, half 1 = o
    {
        const int xrow = tid >> 1;
        const int half = tid & 1;
        if (xrow < nvalid) {
            const int grow = g_perm[slotbase + xrow];
            const float* src = (half ? o : a) + (size_t)grow * 64;
            #pragma unroll
            for (int j = 0; j < 8; j++) {
                float4 v0 = ((const float4*)src)[2 * j];
                float4 v1 = ((const float4*)src)[2 * j + 1];
                uint32_t off = sw_off(xrow, half * 8 + j);
                *(uint4*)(smem + OFF_X + off) = make_uint4(
                    pack2h(v0.x, v0.y), pack2h(v0.z, v0.w),
                    pack2h(v1.x, v1.y), pack2h(v1.z, v1.w));
            }
        } else {
            #pragma unroll
            for (int j = 0; j < 8; j++)
                *(uint4*)(smem + OFF_X + sw_off(xrow, half * 8 + j)) =
                    make_uint4(0, 0, 0, 0);
        }
    }
    __syncthreads();

    float acc2[4][2][4];
    two_layer_mma(smem, smem_base, tid, lane, wm, wn, acc2);
    __syncthreads();

    // epilogue2: D2 -> smem (stride 68), then bias+lrelu+dot(ui)
    float* sD2 = (float*)smem;          // 128*68*4 = 34816 B; X + W0-head dead
    const float* sb1 = (const float*)(smem + OFF_B1);
    #pragma unroll
    for (int i = 0; i < 4; i++) {
        int row0 = wm * 64 + i * 16 + (lane >> 2);
        #pragma unroll
        for (int j = 0; j < 2; j++) {
            int col = wn * 16 + j * 8 + 2 * (lane & 3);
            *(float2*)&sD2[row0 * 68 + col]       = make_float2(acc2[i][j][0], acc2[i][j][1]);
            *(float2*)&sD2[(row0 + 8) * 68 + col] = make_float2(acc2[i][j][2], acc2[i][j][3]);
        }
    }
    __syncthreads();

    if (tid < nvalid) {
        int grow = g_perm[slotbase + tid];
        const float4* uir = (const float4*)(g_ui + (size_t)(grow >> 5) * 64);
        const float* drow = sD2 + tid * 68;
        float s = 0.f;
        #pragma unroll
        for (int c4 = 0; c4 < 16; c4++) {
            float4 uv = uir[c4];
            float v0 = lrelu(drow[4 * c4 + 0] + sb1[4 * c4 + 0]);
            float v1 = lrelu(drow[4 * c4 + 1] + sb1[4 * c4 + 1]);
            float v2 = lrelu(drow[4 * c4 + 2] + sb1[4 * c4 + 2]);
            float v3 = lrelu(drow[4 * c4 + 3] + sb1[4 * c4 + 3]);
            s = fmaf(v0, uv.x, s); s = fmaf(v1, uv.y, s);
            s = fmaf(v2, uv.z, s); s = fmaf(v3, uv.w, s);
        }
        out[grow] = s;
    }
}

// ===========================================================================
extern "C" void kernel_launch(void* const* d_in, const int* in_sizes, int n_in,
                              void* d_out, int out_size) {
    const float* u    = (const float*)d_in[0];
    const float* iv   = (const float*)d_in[1];
    const float* a    = (const float*)d_in[2];
    const float* o    = (const float*)d_in[3];
    const int*   s    = (const int*)  d_in[4];
    const float* aoW0 = (const float*)d_in[5];
    const float* aob0 = (const float*)d_in[6];
    const float* aoW1 = (const float*)d_in[7];
    const float* aob1 = (const float*)d_in[8];
    const float* uiW0 = (const float*)d_in[9];
    const float* uib0 = (const float*)d_in[10];
    const float* uiW1 = (const float*)d_in[11];
    const float* uib1 = (const float*)d_in[12];
    float* out = (float*)d_out;

    cudaFuncSetAttribute((const void*)ui_mma_kernel,
                         cudaFuncAttributeMaxDynamicSharedMemorySize, MM_SMEM);
    cudaFuncSetAttribute((const void*)ao_mma_kernel,
                         cudaFuncAttributeMaxDynamicSharedMemorySize, MM_SMEM);

    init_kernel<<<1, 32>>>();
    scatter_kernel<<<TOT / 256, 256>>>(s);
    prep_w_kernel<<<192, 256>>>(aoW0, aoW1, uiW0, uiW1);
    ui_mma_kernel<<<B_ / 128, 256, MM_SMEM>>>(u, iv, uib0, uib1);
    ao_mma_kernel<<<3 * TOT / 128, 256, MM_SMEM>>>(a, o, aob0, aob1, out);
}

// round 7
// speedup vs baseline: 6.4222x; 1.7091x over previous
#include <cuda_runtime.h>
#include <cuda_fp16.h>
#include <cstdint>

// Model_53283364274775 on GB300 (plain sm_103 PTX target -> no tcgen05):
// single-pass fp16 mma.sync for AO (relation-sorted) and UI branches.
// R7: warp-aggregated scatter, W1 direct fragment LDG, 4-launch chain.

#define B_   8192
#define N_   32
#define TOT  (B_ * N_)          // 262144 = 2^18
#define SLOPE 0.01f

__device__ int   g_pos[3];
__device__ int   g_perm[3 * TOT];
__device__ float g_ui[B_ * 64];
// Pre-swizzled fp16 W0^T images: relations 0..2 = AO, 3 = UI. 32KB each.
__device__ float4 g_wimg[4 * 2048];
// W1 in direct mma B-fragment layout: [rel][wn][kk][lane] uint4
// (.x=j0b0 .y=j0b1 .z=j1b0 .w=j1b1). 16KB per relation.
__device__ uint4 g_w1frag[4 * 1024];

__device__ __forceinline__ float lrelu(float x) { return x >= 0.f ? x : SLOPE * x; }

__device__ __forceinline__ uint32_t smem_to_u32(const void* p) {
    uint32_t a;
    asm("{ .reg .u64 t; cvta.to.shared.u64 t, %1; cvt.u32.u64 %0, t; }"
        : "=r"(a) : "l"(p));
    return a;
}
__device__ __forceinline__ void ldsm_x4(uint32_t& r0, uint32_t& r1,
                                        uint32_t& r2, uint32_t& r3, uint32_t addr) {
    asm volatile("ldmatrix.sync.aligned.m8n8.x4.shared.b16 {%0,%1,%2,%3}, [%4];"
        : "=r"(r0), "=r"(r1), "=r"(r2), "=r"(r3) : "r"(addr));
}
__device__ __forceinline__ void mma_f16(float* d, const uint32_t* a4,
                                        uint32_t b0, uint32_t b1) {
    asm volatile("mma.sync.aligned.m16n8k16.row.col.f32.f16.f16.f32 "
        "{%0,%1,%2,%3}, {%4,%5,%6,%7}, {%8,%9}, {%0,%1,%2,%3};"
        : "+f"(d[0]), "+f"(d[1]), "+f"(d[2]), "+f"(d[3])
        : "r"(a4[0]), "r"(a4[1]), "r"(a4[2]), "r"(a4[3]), "r"(b0), "r"(b1));
}
// 256B rows of fp16, XOR swizzle on 16B chunks: conflict-free ldmatrix
__device__ __forceinline__ uint32_t sw_off(int row, int chunk16) {
    return (uint32_t)(row * 256 + ((chunk16 ^ (row & 7)) << 4));
}
__device__ __forceinline__ uint32_t pack2h(float f0, float f1) {
    return (uint32_t)__half_as_ushort(__float2half_rn(f0)) |
           ((uint32_t)__half_as_ushort(__float2half_rn(f1)) << 16);
}

// ======================= prep_w (+ g_pos init) =============================
__global__ void prep_w_kernel(const float* __restrict__ aoW0,
                              const float* __restrict__ aoW1,
                              const float* __restrict__ uiW0,
                              const float* __restrict__ uiW1) {
    int idx = blockIdx.x * blockDim.x + threadIdx.x;   // 0..49151
    if (blockIdx.x == 0 && threadIdx.x < 3)
        g_pos[threadIdx.x] = threadIdx.x * TOT;        // scatter launches later

    if (idx < 32768) {                 // W0^T smem image: 4 rel x 8192 (k2, n)
        int r = idx >> 13, p = idx & 8191;
        int k2 = p >> 7, n = p & 127;
        const float* W = (r < 3) ? (aoW0 + r * 16384) : uiW0;
        uint32_t hi = pack2h(W[(2 * k2) * 128 + n], W[(2 * k2 + 1) * 128 + n]);
        uint32_t off = sw_off(n, k2 >> 2) + (k2 & 3) * 4;
        *(uint32_t*)((uint8_t*)g_wimg + (size_t)r * 32768 + off) = hi;
    } else if (idx < 49152) {          // W1 fragment layout: 4 rel x 4096 words
        int t = idx - 32768;
        int r = t >> 12, q = t & 4095;
        int w    = q & 3;              // j = w>>1, breg = w&1
        int lane = (q >> 2) & 31;
        int kk   = (q >> 7) & 7;
        int wn   = (q >> 10) & 3;
        const float* W = (r < 3) ? (aoW1 + r * 8192) : uiW1;
        int n = wn * 16 + (w >> 1) * 8 + (lane >> 2);
        int k = kk * 16 + (lane & 3) * 2 + (w & 1) * 8;
        uint32_t v = pack2h(W[k * 64 + n], W[(k + 1) * 64 + n]);
        ((uint32_t*)g_w1frag)[((size_t)r * 1024 + (wn * 8 + kk) * 32 + lane) * 4 + w] = v;
    }
}

// ======================= scatter (warp-aggregated) =========================
__global__ void scatter_kernel(const int* __restrict__ s_raw) {
    __shared__ int sIs64;
    if (threadIdx.x == 0) {
        int nz = 0;
        #pragma unroll
        for (int i = 1; i < 256; i += 2) nz |= s_raw[i];
        sIs64 = (nz == 0) ? 1 : 0;
    }
    __syncthreads();
    int idx = blockIdx.x * blockDim.x + threadIdx.x;
    int lane = threadIdx.x & 31;
    int r = sIs64 ? s_raw[2 * idx] : s_raw[idx];
    unsigned m0 = __ballot_sync(0xffffffffu, r == 0);
    unsigned m1 = __ballot_sync(0xffffffffu, r == 1);
    unsigned mine = (r == 0) ? m0 : (r == 1) ? m1 : ~(m0 | m1);
    int leader = __ffs(mine) - 1;
    int base = 0;
    if (lane == leader) base = atomicAdd(&g_pos[r], __popc(mine));
    base = __shfl_sync(0xffffffffu, base, leader);
    g_perm[base + __popc(mine & ((1u << lane) - 1u))] = idx;
}

// ======================= shared mma machinery ==============================
// smem map (bytes): 0 X(32K) | 32K W0(32K) | 64K b0(512) | 64.5K b1(256)
#define OFF_X    0
#define OFF_W0   32768
#define OFF_B0   65536
#define OFF_B1   66048
#define MM_SMEM  66304

// GEMM1: D(128x128) = X @ W0^T, H=lrelu(D+b0) back into X region.
// GEMM2: acc2 = H @ W1^T (128x64), W1 B-fragments direct from gmem.
__device__ __forceinline__ void two_layer_mma(
    char* smem, uint32_t smem_base, int rel, int tid, int lane, int wm, int wn,
    float (&acc2)[4][2][4])
{
    const float* sb0 = (const float*)(smem + OFF_B0);

    // ---- GEMM1 ----
    float acc[4][4][4];
    #pragma unroll
    for (int i = 0; i < 4; i++)
        #pragma unroll
        for (int j = 0; j < 4; j++)
            #pragma unroll
            for (int q = 0; q < 4; q++) acc[i][j][q] = 0.f;

    {
        const uint32_t Ab = smem_base + OFF_X;
        const uint32_t Bb = smem_base + OFF_W0;
        #pragma unroll
        for (int kk = 0; kk < 8; kk++) {
            const int chunk = kk * 2 + (lane >> 4);
            uint32_t af[4][4];
            #pragma unroll
            for (int i = 0; i < 4; i++) {
                int row = wm * 64 + i * 16 + (lane & 15);
                ldsm_x4(af[i][0], af[i][1], af[i][2], af[i][3],
                        Ab + sw_off(row, chunk));
            }
            uint32_t bf[4][2];
            #pragma unroll
            for (int h = 0; h < 2; h++) {
                int nrow = wn * 32 + h * 16 + (lane & 7) + ((lane >> 3) & 1) * 8;
                uint32_t r0, r1, r2, r3;
                ldsm_x4(r0, r1, r2, r3, Bb + sw_off(nrow, chunk));
                bf[h * 2][0] = r0; bf[h * 2][1] = r2;
                bf[h * 2 + 1][0] = r1; bf[h * 2 + 1][1] = r3;
            }
            #pragma unroll
            for (int i = 0; i < 4; i++)
                #pragma unroll
                for (int j = 0; j < 4; j++)
                    mma_f16(acc[i][j], af[i], bf[j][0], bf[j][1]);
        }
    }
    __syncthreads();

    // ---- epilogue1: H = lrelu(D + b0) -> fp16 into X region ----
    #pragma unroll
    for (int i = 0; i < 4; i++) {
        int row0 = wm * 64 + i * 16 + (lane >> 2);
        #pragma unroll
        for (int j = 0; j < 4; j++) {
            int col = wn * 32 + j * 8 + 2 * (lane & 3);
            float bv0 = sb0[col], bv1 = sb0[col + 1];
            uint32_t h0 = pack2h(lrelu(acc[i][j][0] + bv0), lrelu(acc[i][j][1] + bv1));
            uint32_t h1 = pack2h(lrelu(acc[i][j][2] + bv0), lrelu(acc[i][j][3] + bv1));
            uint32_t o0 = sw_off(row0, col >> 3) + ((2 * col) & 15);
            uint32_t o1 = sw_off(row0 + 8, col >> 3) + ((2 * col) & 15);
            *(uint32_t*)(smem + OFF_X + o0) = h0;
            *(uint32_t*)(smem + OFF_X + o1) = h1;
        }
    }

    // W1 fragments: 8 coalesced uint4 per lane (L2-resident, 16KB/relation)
    uint4 w1f[8];
    {
        const uint4* wp = g_w1frag + (size_t)rel * 1024 + wn * 256 + lane;
        #pragma unroll
        for (int kk = 0; kk < 8; kk++) w1f[kk] = wp[kk * 32];
    }
    __syncthreads();

    // ---- GEMM2 ----
    #pragma unroll
    for (int i = 0; i < 4; i++)
        #pragma unroll
        for (int j = 0; j < 2; j++)
            #pragma unroll
            for (int q = 0; q < 4; q++) acc2[i][j][q] = 0.f;

    {
        const uint32_t Ab = smem_base + OFF_X;
        #pragma unroll
        for (int kk = 0; kk < 8; kk++) {
            const int chunk = kk * 2 + (lane >> 4);
            uint32_t af[4][4];
            #pragma unroll
            for (int i = 0; i < 4; i++) {
                int row = wm * 64 + i * 16 + (lane & 15);
                ldsm_x4(af[i][0], af[i][1], af[i][2], af[i][3],
                        Ab + sw_off(row, chunk));
            }
            #pragma unroll
            for (int i = 0; i < 4; i++) {
                mma_f16(acc2[i][0], af[i], w1f[kk].x, w1f[kk].y);
                mma_f16(acc2[i][1], af[i], w1f[kk].z, w1f[kk].w);
            }
        }
    }
}

__device__ __forceinline__ void load_weights(char* smem, int r, int tid,
                                             const float* b0, const float* b1) {
    const float4* wsrc = g_wimg + (size_t)r * 2048;
    float4* wdst = (float4*)(smem + OFF_W0);
    #pragma unroll 4
    for (int idx = tid; idx < 2048; idx += 256) wdst[idx] = wsrc[idx];
    if (tid < 128) ((float*)(smem + OFF_B0))[tid] = b0[tid];
    if (tid < 64)  ((float*)(smem + OFF_B1))[tid] = b1[tid];
}

// ======================= UI branch (mma) ===================================
__global__ void __launch_bounds__(256, 2) ui_mma_kernel(
    const float* __restrict__ u, const float* __restrict__ iv,
    const float* __restrict__ b0, const float* __restrict__ b1)
{
    extern __shared__ char smem[];
    const uint32_t smem_base = smem_to_u32(smem);
    const int tid = threadIdx.x;
    const int lane = tid & 31;
    const int wm = (tid >> 5) & 1;
    const int wn = tid >> 6;
    const int rowbase = blockIdx.x * 128;

    load_weights(smem, 3, tid, b0, b1);

    // X gather: thread = half a row; half 0 = u (k 0..63), half 1 = i
    {
        const int xrow = tid >> 1;
        const int half = tid & 1;
        const float* src = (half ? iv : u) + (size_t)(rowbase + xrow) * 64;
        #pragma unroll
        for (int j = 0; j < 8; j++) {
            float4 v0 = ((const float4*)src)[2 * j];
            float4 v1 = ((const float4*)src)[2 * j + 1];
            uint32_t off = sw_off(xrow, half * 8 + j);
            *(uint4*)(smem + OFF_X + off) = make_uint4(
                pack2h(v0.x, v0.y), pack2h(v0.z, v0.w),
                pack2h(v1.x, v1.y), pack2h(v1.z, v1.w));
        }
    }
    __syncthreads();

    float acc2[4][2][4];
    two_layer_mma(smem, smem_base, 3, tid, lane, wm, wn, acc2);

    // epilogue: g_ui = lrelu(D2 + b1) straight from fragments
    const float* sb1 = (const float*)(smem + OFF_B1);
    #pragma unroll
    for (int i = 0; i < 4; i++) {
        int row0 = wm * 64 + i * 16 + (lane >> 2);
        #pragma unroll
        for (int j = 0; j < 2; j++) {
            int col = wn * 16 + j * 8 + 2 * (lane & 3);
            float bv0 = sb1[col], bv1 = sb1[col + 1];
            *(float2*)&g_ui[(size_t)(rowbase + row0) * 64 + col] =
                make_float2(lrelu(acc2[i][j][0] + bv0), lrelu(acc2[i][j][1] + bv1));
            *(float2*)&g_ui[(size_t)(rowbase + row0 + 8) * 64 + col] =
                make_float2(lrelu(acc2[i][j][2] + bv0), lrelu(acc2[i][j][3] + bv1));
        }
    }
}

// ======================= AO branch (mma) ===================================
__global__ void __launch_bounds__(256, 2) ao_mma_kernel(
    const float* __restrict__ a, const float* __restrict__ o,
    const float* __restrict__ b0, const float* __restrict__ b1,
    float* __restrict__ out)
{
    extern __shared__ char smem[];
    const uint32_t smem_base = smem_to_u32(smem);
    const int tid = threadIdx.x;
    const int lane = tid & 31;
    const int wm = (tid >> 5) & 1;
    const int wn = tid >> 6;
    const int slotbase = blockIdx.x * 128;      // absolute in [0, 3*TOT)
    const int r = slotbase >> 18;               // TOT = 2^18
    const int local = slotbase & (TOT - 1);
    const int count = g_pos[r] - r * TOT;
    if (local >= count) return;                 // empty tail CTA
    const int nvalid = min(128, count - local);

    load_weights(smem, r, tid, b0 + r * 128, b1 + r * 64);

    // X gather: thread = half a row; half 0 = a, half 1 = o
    {
        const int xrow = tid >> 1;
        const int half = tid & 1;
        if (xrow < nvalid) {
            const int grow = g_perm[slotbase + xrow];
            const float* src = (half ? o : a) + (size_t)grow * 64;
            #pragma unroll
            for (int j = 0; j < 8; j++) {
                float4 v0 = ((const float4*)src)[2 * j];
                float4 v1 = ((const float4*)src)[2 * j + 1];
                uint32_t off = sw_off(xrow, half * 8 + j);
                *(uint4*)(smem + OFF_X + off) = make_uint4(
                    pack2h(v0.x, v0.y), pack2h(v0.z, v0.w),
                    pack2h(v1.x, v1.y), pack2h(v1.z, v1.w));
            }
        } else {
            #pragma unroll
            for (int j = 0; j < 8; j++)
                *(uint4*)(smem + OFF_X + sw_off(xrow, half * 8 + j)) =
                    make_uint4(0, 0, 0, 0);
        }
    }
    __syncthreads();

    float acc2[4][2][4];
    two_layer_mma(smem, smem_base, r, tid, lane, wm, wn, acc2);
    __syncthreads();

    // epilogue2: D2 -> smem (stride 68), then bias+lrelu+dot(ui)
    float* sD2 = (float*)smem;          // 34816 B; X/W0 regions dead now
    const float* sb1 = (const float*)(smem + OFF_B1);
    #pragma unroll
    for (int i = 0; i < 4; i++) {
        int row0 = wm * 64 + i * 16 + (lane >> 2);
        #pragma unroll
        for (int j = 0; j < 2; j++) {
            int col = wn * 16 + j * 8 + 2 * (lane & 3);
            *(float2*)&sD2[row0 * 68 + col]       = make_float2(acc2[i][j][0], acc2[i][j][1]);
            *(float2*)&sD2[(row0 + 8) * 68 + col] = make_float2(acc2[i][j][2], acc2[i][j][3]);
        }
    }
    __syncthreads();

    if (tid < nvalid) {
        int grow = g_perm[slotbase + tid];
        const float4* uir = (const float4*)(g_ui + (size_t)(grow >> 5) * 64);
        const float* drow = sD2 + tid * 68;
        float s = 0.f;
        #pragma unroll
        for (int c4 = 0; c4 < 16; c4++) {
            float4 uv = uir[c4];
            float v0 = lrelu(drow[4 * c4 + 0] + sb1[4 * c4 + 0]);
            float v1 = lrelu(drow[4 * c4 + 1] + sb1[4 * c4 + 1]);
            float v2 = lrelu(drow[4 * c4 + 2] + sb1[4 * c4 + 2]);
            float v3 = lrelu(drow[4 * c4 + 3] + sb1[4 * c4 + 3]);
            s = fmaf(v0, uv.x, s); s = fmaf(v1, uv.y, s);
            s = fmaf(v2, uv.z, s); s = fmaf(v3, uv.w, s);
        }
        out[grow] = s;
    }
}

// ===========================================================================
extern "C" void kernel_launch(void* const* d_in, const int* in_sizes, int n_in,
                              void* d_out, int out_size) {
    const float* u    = (const float*)d_in[0];
    const float* iv   = (const float*)d_in[1];
    const float* a    = (const float*)d_in[2];
    const float* o    = (const float*)d_in[3];
    const int*   s    = (const int*)  d_in[4];
    const float* aoW0 = (const float*)d_in[5];
    const float* aob0 = (const float*)d_in[6];
    const float* aoW1 = (const float*)d_in[7];
    const float* aob1 = (const float*)d_in[8];
    const float* uiW0 = (const float*)d_in[9];
    const float* uib0 = (const float*)d_in[10];
    const float* uiW1 = (const float*)d_in[11];
    const float* uib1 = (const float*)d_in[12];
    float* out = (float*)d_out;

    cudaFuncSetAttribute((const void*)ui_mma_kernel,
                         cudaFuncAttributeMaxDynamicSharedMemorySize, MM_SMEM);
    cudaFuncSetAttribute((const void*)ao_mma_kernel,
                         cudaFuncAttributeMaxDynamicSharedMemorySize, MM_SMEM);

    // order: prep_w(+init) -> ui -> scatter -> ao  (ao is launch #4: profiled)
    prep_w_kernel<<<192, 256>>>(aoW0, aoW1, uiW0, uiW1);
    ui_mma_kernel<<<B_ / 128, 256, MM_SMEM>>>(u, iv, uib0, uib1);
    scatter_kernel<<<TOT / 256, 256>>>(s);
    ao_mma_kernel<<<3 * TOT / 128, 256, MM_SMEM>>>(a, o, aob0, aob1, out);
}

// round 8
// speedup vs baseline: 7.1703x; 1.1165x over previous
#include <cuda_runtime.h>
#include <cuda_fp16.h>
#include <cstdint>

// Model_53283364274775 on GB300 (plain sm_103 PTX target -> no tcgen05):
// single-pass fp16 mma.sync. R8: 256 rows/CTA in AO (shared weights across
// two 128-row blocks), scatter fused into UI launch, 3-launch chain.

#define B_   8192
#define N_   32
#define TOT  (B_ * N_)          // 262144 = 2^18
#define SLOPE 0.01f

__device__ int   g_pos[3];
__device__ int   g_perm[3 * TOT];
__device__ float g_ui[B_ * 64];
// Pre-swizzled fp16 W0^T images: relations 0..2 = AO, 3 = UI. 32KB each.
__device__ float4 g_wimg[4 * 2048];
// W1 in direct mma B-fragment layout: [rel][wn][kk][lane] uint4
__device__ uint4 g_w1frag[4 * 1024];

__device__ __forceinline__ float lrelu(float x) { return x >= 0.f ? x : SLOPE * x; }

__device__ __forceinline__ uint32_t smem_to_u32(const void* p) {
    uint32_t a;
    asm("{ .reg .u64 t; cvta.to.shared.u64 t, %1; cvt.u32.u64 %0, t; }"
        : "=r"(a) : "l"(p));
    return a;
}
__device__ __forceinline__ void ldsm_x4(uint32_t& r0, uint32_t& r1,
                                        uint32_t& r2, uint32_t& r3, uint32_t addr) {
    asm volatile("ldmatrix.sync.aligned.m8n8.x4.shared.b16 {%0,%1,%2,%3}, [%4];"
        : "=r"(r0), "=r"(r1), "=r"(r2), "=r"(r3) : "r"(addr));
}
__device__ __forceinline__ void mma_f16(float* d, const uint32_t* a4,
                                        uint32_t b0, uint32_t b1) {
    asm volatile("mma.sync.aligned.m16n8k16.row.col.f32.f16.f16.f32 "
        "{%0,%1,%2,%3}, {%4,%5,%6,%7}, {%8,%9}, {%0,%1,%2,%3};"
        : "+f"(d[0]), "+f"(d[1]), "+f"(d[2]), "+f"(d[3])
        : "r"(a4[0]), "r"(a4[1]), "r"(a4[2]), "r"(a4[3]), "r"(b0), "r"(b1));
}
// 256B rows of fp16, XOR swizzle on 16B chunks: conflict-free ldmatrix
__device__ __forceinline__ uint32_t sw_off(int row, int chunk16) {
    return (uint32_t)(row * 256 + ((chunk16 ^ (row & 7)) << 4));
}
__device__ __forceinline__ uint32_t pack2h(float f0, float f1) {
    return (uint32_t)__half_as_ushort(__float2half_rn(f0)) |
           ((uint32_t)__half_as_ushort(__float2half_rn(f1)) << 16);
}

// smem layout (bytes): b0 @0 (512) | b1 @512 (256) | X1 @1024 (32K)
//                      | W0 @33792 (32K) | X2 @66560 (32K, AO only)
#define OFF_B0   0
#define OFF_B1   512
#define OFF_X1   1024
#define OFF_W0   33792
#define OFF_X2   66560
#define SM_UI    66560
#define SM_AO    99328

// ======================= prep_w (+ g_pos init) =============================
__global__ void prep_w_kernel(const float* __restrict__ aoW0,
                              const float* __restrict__ aoW1,
                              const float* __restrict__ uiW0,
                              const float* __restrict__ uiW1) {
    int idx = blockIdx.x * blockDim.x + threadIdx.x;   // 0..49151
    if (blockIdx.x == 0 && threadIdx.x < 3)
        g_pos[threadIdx.x] = threadIdx.x * TOT;

    if (idx < 32768) {                 // W0^T smem image: 4 rel x 8192 (k2, n)
        int r = idx >> 13, p = idx & 8191;
        int k2 = p >> 7, n = p & 127;
        const float* W = (r < 3) ? (aoW0 + r * 16384) : uiW0;
        uint32_t hi = pack2h(W[(2 * k2) * 128 + n], W[(2 * k2 + 1) * 128 + n]);
        uint32_t off = sw_off(n, k2 >> 2) + (k2 & 3) * 4;
        *(uint32_t*)((uint8_t*)g_wimg + (size_t)r * 32768 + off) = hi;
    } else if (idx < 49152) {          // W1 fragment layout: 4 rel x 4096 words
        int t = idx - 32768;
        int r = t >> 12, q = t & 4095;
        int w    = q & 3;
        int lane = (q >> 2) & 31;
        int kk   = (q >> 7) & 7;
        int wn   = (q >> 10) & 3;
        const float* W = (r < 3) ? (aoW1 + r * 8192) : uiW1;
        int n = wn * 16 + (w >> 1) * 8 + (lane >> 2);
        int k = kk * 16 + (lane & 3) * 2 + (w & 1) * 8;
        uint32_t v = pack2h(W[k * 64 + n], W[(k + 1) * 64 + n]);
        ((uint32_t*)g_w1frag)[((size_t)r * 1024 + (wn * 8 + kk) * 32 + lane) * 4 + w] = v;
    }
}

// ======================= shared mma machinery ==============================
// GEMM1: D = X @ W0^T (W0 smem @OFF_W0), H=lrelu(D+b0) back into X region.
// GEMM2: acc2 = H @ W1^T, W1 B-fragments direct from gmem.
__device__ __forceinline__ void two_layer_mma(
    char* smem, uint32_t smem_base, int rel, int lane, int wm, int wn,
    uint32_t xoff, float (&acc2)[4][2][4])
{
    const float* sb0 = (const float*)(smem + OFF_B0);

    float acc[4][4][4];
    #pragma unroll
    for (int i = 0; i < 4; i++)
        #pragma unroll
        for (int j = 0; j < 4; j++)
            #pragma unroll
            for (int q = 0; q < 4; q++) acc[i][j][q] = 0.f;

    {
        const uint32_t Ab = smem_base + xoff;
        const uint32_t Bb = smem_base + OFF_W0;
        #pragma unroll
        for (int kk = 0; kk < 8; kk++) {
            const int chunk = kk * 2 + (lane >> 4);
            uint32_t af[4][4];
            #pragma unroll
            for (int i = 0; i < 4; i++) {
                int row = wm * 64 + i * 16 + (lane & 15);
                ldsm_x4(af[i][0], af[i][1], af[i][2], af[i][3],
                        Ab + sw_off(row, chunk));
            }
            uint32_t bf[4][2];
            #pragma unroll
            for (int h = 0; h < 2; h++) {
                int nrow = wn * 32 + h * 16 + (lane & 7) + ((lane >> 3) & 1) * 8;
                uint32_t r0, r1, r2, r3;
                ldsm_x4(r0, r1, r2, r3, Bb + sw_off(nrow, chunk));
                bf[h * 2][0] = r0; bf[h * 2][1] = r2;
                bf[h * 2 + 1][0] = r1; bf[h * 2 + 1][1] = r3;
            }
            #pragma unroll
            for (int i = 0; i < 4; i++)
                #pragma unroll
                for (int j = 0; j < 4; j++)
                    mma_f16(acc[i][j], af[i], bf[j][0], bf[j][1]);
        }
    }
    __syncthreads();

    // epilogue1: H = lrelu(D + b0) -> fp16 into X region
    #pragma unroll
    for (int i = 0; i < 4; i++) {
        int row0 = wm * 64 + i * 16 + (lane >> 2);
        #pragma unroll
        for (int j = 0; j < 4; j++) {
            int col = wn * 32 + j * 8 + 2 * (lane & 3);
            float bv0 = sb0[col], bv1 = sb0[col + 1];
            uint32_t h0 = pack2h(lrelu(acc[i][j][0] + bv0), lrelu(acc[i][j][1] + bv1));
            uint32_t h1 = pack2h(lrelu(acc[i][j][2] + bv0), lrelu(acc[i][j][3] + bv1));
            uint32_t o0 = sw_off(row0, col >> 3) + ((2 * col) & 15);
            uint32_t o1 = sw_off(row0 + 8, col >> 3) + ((2 * col) & 15);
            *(uint32_t*)(smem + xoff + o0) = h0;
            *(uint32_t*)(smem + xoff + o1) = h1;
        }
    }

    // W1 fragments: 8 coalesced uint4 per lane (L2-hot)
    uint4 w1f[8];
    {
        const uint4* wp = g_w1frag + (size_t)rel * 1024 + wn * 256 + lane;
        #pragma unroll
        for (int kk = 0; kk < 8; kk++) w1f[kk] = wp[kk * 32];
    }
    __syncthreads();

    #pragma unroll
    for (int i = 0; i < 4; i++)
        #pragma unroll
        for (int j = 0; j < 2; j++)
            #pragma unroll
            for (int q = 0; q < 4; q++) acc2[i][j][q] = 0.f;

    {
        const uint32_t Ab = smem_base + xoff;
        #pragma unroll
        for (int kk = 0; kk < 8; kk++) {
            const int chunk = kk * 2 + (lane >> 4);
            uint32_t af[4][4];
            #pragma unroll
            for (int i = 0; i < 4; i++) {
                int row = wm * 64 + i * 16 + (lane & 15);
                ldsm_x4(af[i][0], af[i][1], af[i][2], af[i][3],
                        Ab + sw_off(row, chunk));
            }
            #pragma unroll
            for (int i = 0; i < 4; i++) {
                mma_f16(acc2[i][0], af[i], w1f[kk].x, w1f[kk].y);
                mma_f16(acc2[i][1], af[i], w1f[kk].z, w1f[kk].w);
            }
        }
    }
}

__device__ __forceinline__ void load_weights(char* smem, int r, int tid,
                                             const float* b0, const float* b1) {
    const float4* wsrc = g_wimg + (size_t)r * 2048;
    float4* wdst = (float4*)(smem + OFF_W0);
    #pragma unroll 4
    for (int idx = tid; idx < 2048; idx += 256) wdst[idx] = wsrc[idx];
    if (tid < 128) ((float*)(smem + OFF_B0))[tid] = b0[tid];
    if (tid < 64)  ((float*)(smem + OFF_B1))[tid] = b1[tid];
}

// ======================= UI branch + scatter (fused) =======================
__global__ void __launch_bounds__(256, 2) ui_scatter_kernel(
    const float* __restrict__ u, const float* __restrict__ iv,
    const float* __restrict__ b0, const float* __restrict__ b1,
    const int* __restrict__ s_raw)
{
    extern __shared__ char smem[];
    const int tid = threadIdx.x;

    if (blockIdx.x >= 64) {
        // ---- scatter path (warp-aggregated bucket sort) ----
        __shared__ int sIs64;
        if (tid == 0) {
            int nz = 0;
            #pragma unroll
            for (int i = 1; i < 256; i += 2) nz |= s_raw[i];
            sIs64 = (nz == 0) ? 1 : 0;
        }
        __syncthreads();
        int idx = (blockIdx.x - 64) * 256 + tid;
        int lane = tid & 31;
        int r = sIs64 ? s_raw[2 * idx] : s_raw[idx];
        unsigned m0 = __ballot_sync(0xffffffffu, r == 0);
        unsigned m1 = __ballot_sync(0xffffffffu, r == 1);
        unsigned mine = (r == 0) ? m0 : (r == 1) ? m1 : ~(m0 | m1);
        int leader = __ffs(mine) - 1;
        int base = 0;
        if (lane == leader) base = atomicAdd(&g_pos[r], __popc(mine));
        base = __shfl_sync(0xffffffffu, base, leader);
        g_perm[base + __popc(mine & ((1u << lane) - 1u))] = idx;
        return;
    }

    // ---- UI path ----
    const uint32_t smem_base = smem_to_u32(smem);
    const int lane = tid & 31;
    const int wm = (tid >> 5) & 1;
    const int wn = tid >> 6;
    const int rowbase = blockIdx.x * 128;

    load_weights(smem, 3, tid, b0, b1);
    {
        const int xrow = tid >> 1;
        const int half = tid & 1;
        const float* src = (half ? iv : u) + (size_t)(rowbase + xrow) * 64;
        #pragma unroll
        for (int j = 0; j < 8; j++) {
            float4 v0 = ((const float4*)src)[2 * j];
            float4 v1 = ((const float4*)src)[2 * j + 1];
            uint32_t off = sw_off(xrow, half * 8 + j);
            *(uint4*)(smem + OFF_X1 + off) = make_uint4(
                pack2h(v0.x, v0.y), pack2h(v0.z, v0.w),
                pack2h(v1.x, v1.y), pack2h(v1.z, v1.w));
        }
    }
    __syncthreads();

    float acc2[4][2][4];
    two_layer_mma(smem, smem_base, 3, lane, wm, wn, OFF_X1, acc2);

    const float* sb1 = (const float*)(smem + OFF_B1);
    #pragma unroll
    for (int i = 0; i < 4; i++) {
        int row0 = wm * 64 + i * 16 + (lane >> 2);
        #pragma unroll
        for (int j = 0; j < 2; j++) {
            int col = wn * 16 + j * 8 + 2 * (lane & 3);
            float bv0 = sb1[col], bv1 = sb1[col + 1];
            *(float2*)&g_ui[(size_t)(rowbase + row0) * 64 + col] =
                make_float2(lrelu(acc2[i][j][0] + bv0), lrelu(acc2[i][j][1] + bv1));
            *(float2*)&g_ui[(size_t)(rowbase + row0 + 8) * 64 + col] =
                make_float2(lrelu(acc2[i][j][2] + bv0), lrelu(acc2[i][j][3] + bv1));
        }
    }
}

// ======================= AO branch: 256 rows per CTA =======================
__global__ void __launch_bounds__(256, 2) ao_mma_kernel(
    const float* __restrict__ a, const float* __restrict__ o,
    const float* __restrict__ b0, const float* __restrict__ b1,
    float* __restrict__ out)
{
    extern __shared__ char smem[];
    const uint32_t smem_base = smem_to_u32(smem);
    const int tid = threadIdx.x;
    const int lane = tid & 31;
    const int wm = (tid >> 5) & 1;
    const int wn = tid >> 6;
    const int slotbase = blockIdx.x * 256;      // absolute in [0, 3*TOT)
    const int r = slotbase >> 18;               // TOT = 2^18
    const int local = slotbase & (TOT - 1);
    const int count = g_pos[r] - r * TOT;
    if (local >= count) return;
    const int nvalid = min(256, count - local);

    load_weights(smem, r, tid, b0 + r * 128, b1 + r * 64);

    // gather X for both blocks: thread = half a row of each block
    {
        const int xrow = tid >> 1;
        const int half = tid & 1;
        #pragma unroll
        for (int bi = 0; bi < 2; bi++) {
            uint32_t xoff = bi ? OFF_X2 : OFF_X1;
            if (bi * 128 + xrow < nvalid) {
                const int grow = g_perm[slotbase + bi * 128 + xrow];
                const float* src = (half ? o : a) + (size_t)grow * 64;
                #pragma unroll
                for (int j = 0; j < 8; j++) {
                    float4 v0 = ((const float4*)src)[2 * j];
                    float4 v1 = ((const float4*)src)[2 * j + 1];
                    uint32_t off = sw_off(xrow, half * 8 + j);
                    *(uint4*)(smem + xoff + off) = make_uint4(
                        pack2h(v0.x, v0.y), pack2h(v0.z, v0.w),
                        pack2h(v1.x, v1.y), pack2h(v1.z, v1.w));
                }
            } else {
                #pragma unroll
                for (int j = 0; j < 8; j++)
                    *(uint4*)(smem + xoff + sw_off(xrow, half * 8 + j)) =
                        make_uint4(0, 0, 0, 0);
            }
        }
    }
    __syncthreads();

    const float* sb1 = (const float*)(smem + OFF_B1);

    #pragma unroll 1
    for (int bi = 0; bi < 2; bi++) {
        if (bi * 128 >= nvalid) break;
        const uint32_t xoff = bi ? OFF_X2 : OFF_X1;
        float acc2[4][2][4];
        two_layer_mma(smem, smem_base, r, lane, wm, wn, xoff, acc2);
        __syncthreads();

        // epilogue2: stage D2 (stride 68).
        // block0 -> @X1 (clobbers 2KB of W0 head, reloaded below)
        // block1 -> @W0 (W0 dead; overruns 2KB into dead X2 head)
        float* sD2 = (float*)(smem + (bi ? OFF_W0 : OFF_X1));
        #pragma unroll
        for (int i = 0; i < 4; i++) {
            int row0 = wm * 64 + i * 16 + (lane >> 2);
            #pragma unroll
            for (int j = 0; j < 2; j++) {
                int col = wn * 16 + j * 8 + 2 * (lane & 3);
                *(float2*)&sD2[row0 * 68 + col] =
                    make_float2(acc2[i][j][0], acc2[i][j][1]);
                *(float2*)&sD2[(row0 + 8) * 68 + col] =
                    make_float2(acc2[i][j][2], acc2[i][j][3]);
            }
        }
        __syncthreads();

        if (tid < 128 && bi * 128 + tid < nvalid) {
            int grow = g_perm[slotbase + bi * 128 + tid];
            const float4* uir = (const float4*)(g_ui + (size_t)(grow >> 5) * 64);
            const float* drow = sD2 + tid * 68;
            float sdot = 0.f;
            #pragma unroll
            for (int c4 = 0; c4 < 16; c4++) {
                float4 uv = uir[c4];
                float v0 = lrelu(drow[4 * c4 + 0] + sb1[4 * c4 + 0]);
                float v1 = lrelu(drow[4 * c4 + 1] + sb1[4 * c4 + 1]);
                float v2 = lrelu(drow[4 * c4 + 2] + sb1[4 * c4 + 2]);
                float v3 = lrelu(drow[4 * c4 + 3] + sb1[4 * c4 + 3]);
                sdot = fmaf(v0, uv.x, sdot); sdot = fmaf(v1, uv.y, sdot);
                sdot = fmaf(v2, uv.z, sdot); sdot = fmaf(v3, uv.w, sdot);
            }
            out[grow] = sdot;
        }
        __syncthreads();

        if (bi == 0) {
            // reload the clobbered 2KB head of W0 before block 2's GEMM1
            const float4* wsrc = g_wimg + (size_t)r * 2048;
            float4* wdst = (float4*)(smem + OFF_W0);
            if (tid < 128) wdst[tid] = wsrc[tid];
            __syncthreads();
        }
    }
}

// ===========================================================================
extern "C" void kernel_launch(void* const* d_in, const int* in_sizes, int n_in,
                              void* d_out, int out_size) {
    const float* u    = (const float*)d_in[0];
    const float* iv   = (const float*)d_in[1];
    const float* a    = (const float*)d_in[2];
    const float* o    = (const float*)d_in[3];
    const int*   s    = (const int*)  d_in[4];
    const float* aoW0 = (const float*)d_in[5];
    const float* aob0 = (const float*)d_in[6];
    const float* aoW1 = (const float*)d_in[7];
    const float* aob1 = (const float*)d_in[8];
    const float* uiW0 = (const float*)d_in[9];
    const float* uib0 = (const float*)d_in[10];
    const float* uiW1 = (const float*)d_in[11];
    const float* uib1 = (const float*)d_in[12];
    float* out = (float*)d_out;

    cudaFuncSetAttribute((const void*)ui_scatter_kernel,
                         cudaFuncAttributeMaxDynamicSharedMemorySize, SM_UI);
    cudaFuncSetAttribute((const void*)ao_mma_kernel,
                         cudaFuncAttributeMaxDynamicSharedMemorySize, SM_AO);

    prep_w_kernel<<<192, 256>>>(aoW0, aoW1, uiW0, uiW1);
    ui_scatter_kernel<<<64 + TOT / 256, 256, SM_UI>>>(u, iv, uib0, uib1, s);
    ao_mma_kernel<<<3 * TOT / 256, 256, SM_AO>>>(a, o, aob0, aob1, out);
}